// round 1
// baseline (speedup 1.0000x reference)
#include <cuda_runtime.h>
#include <math.h>

// Problem constants
#define B_    2
#define D_    5
#define H_    32
#define W_    32
#define C_    256
#define NH_   8
#define NL_   5
#define NP_   16
#define HD_   32
#define HW_   (H_*W_)          // 1024
#define LQ_   (D_*HW_)         // 5120
#define M_    (B_*LQ_)         // 10240
#define MLP_H_ 1024

// Scratch (static device globals; no allocation in kernel_launch)
__device__ float g_q   [M_*C_];                 // LN3 output
__device__ float g_val [M_*C_];                 // value projection
__device__ float g_off [M_*NH_*NL_*NP_*2];      // offsets (10240 x 1280)
__device__ float g_attn[M_*NH_*NL_*NP_];        // attn logits -> softmax (10240 x 640)
__device__ float g_samp[M_*C_];                 // sampled attention (pre out-proj)
__device__ float g_h   [M_*C_];                 // LN4 output
__device__ float g_mlp [M_*MLP_H_];             // fc1+GELU output

// ---------------------------------------------------------------------------
// LayerNorm: one block (256 threads) per row of 256 channels
// ---------------------------------------------------------------------------
__global__ void ln_kernel(const float* __restrict__ x,
                          const float* __restrict__ g,
                          const float* __restrict__ b,
                          float* __restrict__ out)
{
    int row = blockIdx.x;
    int c   = threadIdx.x;
    float v = x[(size_t)row*C_ + c];
    float sum = v, sq = v*v;
    #pragma unroll
    for (int o = 16; o > 0; o >>= 1) {
        sum += __shfl_xor_sync(0xffffffffu, sum, o);
        sq  += __shfl_xor_sync(0xffffffffu, sq , o);
    }
    __shared__ float s1[8], s2[8];
    int w = c >> 5, l = c & 31;
    if (l == 0) { s1[w] = sum; s2[w] = sq; }
    __syncthreads();
    sum = 0.f; sq = 0.f;
    #pragma unroll
    for (int i = 0; i < 8; i++) { sum += s1[i]; sq += s2[i]; }
    float m   = sum * (1.f / C_);
    float var = sq  * (1.f / C_) - m*m;
    float inv = rsqrtf(var + 1e-5f);
    out[(size_t)row*C_ + c] = (v - m) * inv * g[c] + b[c];
}

// ---------------------------------------------------------------------------
// Tiled SGEMM: C[M,N] = A[M,K] @ B[K,N] + bias (+GELU) (+res)
// BM=BN=128, BK=8, 256 threads, 8x8 per thread. All dims divisible.
// ACT: 0 = none, 1 = exact GELU.  RES: 0/1 add residual [M,N].
// ---------------------------------------------------------------------------
template<int ACT, int RES>
__global__ void __launch_bounds__(256, 2) sgemm_kernel(
    int M, int N, int K,
    const float* __restrict__ A,
    const float* __restrict__ Bm,
    const float* __restrict__ bias,
    const float* __restrict__ res,
    float* __restrict__ C)
{
    const int BM = 128, BN = 128, BK = 8;
    __shared__ float As[BK][BM];
    __shared__ float Bs[BK][BN];

    int tid  = threadIdx.x;
    int brow = blockIdx.y * BM;
    int bcol = blockIdx.x * BN;
    int tx = tid & 15;        // 16 col groups of 8
    int ty = tid >> 4;        // 16 row groups of 8

    int a_r = tid >> 1;            // [0,128)
    int a_c = (tid & 1) * 4;       // {0,4}
    int b_r = tid >> 5;            // [0,8)
    int b_c = (tid & 31) * 4;      // {0..124}

    const float* Ap = A  + (size_t)(brow + a_r) * K + a_c;
    const float* Bp = Bm + (size_t)b_r * N + bcol + b_c;

    float acc[8][8];
    #pragma unroll
    for (int i = 0; i < 8; i++)
        #pragma unroll
        for (int j = 0; j < 8; j++) acc[i][j] = 0.f;

    for (int k0 = 0; k0 < K; k0 += BK) {
        float4 av = *(const float4*)(Ap + k0);
        float4 bv = *(const float4*)(Bp + (size_t)k0 * N);
        As[a_c+0][a_r] = av.x;
        As[a_c+1][a_r] = av.y;
        As[a_c+2][a_r] = av.z;
        As[a_c+3][a_r] = av.w;
        *(float4*)&Bs[b_r][b_c] = bv;
        __syncthreads();

        #pragma unroll
        for (int kk = 0; kk < BK; kk++) {
            float a[8], b[8];
            #pragma unroll
            for (int i = 0; i < 8; i++) a[i] = As[kk][ty*8 + i];
            #pragma unroll
            for (int j = 0; j < 8; j++) b[j] = Bs[kk][tx*8 + j];
            #pragma unroll
            for (int i = 0; i < 8; i++)
                #pragma unroll
                for (int j = 0; j < 8; j++)
                    acc[i][j] += a[i] * b[j];
        }
        __syncthreads();
    }

    #pragma unroll
    for (int i = 0; i < 8; i++) {
        int r = brow + ty*8 + i;
        #pragma unroll
        for (int j = 0; j < 8; j++) {
            int col = bcol + tx*8 + j;
            float v = acc[i][j] + bias[col];
            if (ACT == 1) v = 0.5f * v * (1.f + erff(v * 0.70710678118654752f));
            if (RES)      v += res[(size_t)r * N + col];
            C[(size_t)r * N + col] = v;
        }
    }
}

// ---------------------------------------------------------------------------
// Softmax over 80 logits per (token, head). 256 threads = 8 warps = 8 heads.
// ---------------------------------------------------------------------------
__global__ void softmax_kernel(float* __restrict__ a)
{
    int row  = blockIdx.x;
    int h    = threadIdx.x >> 5;
    int lane = threadIdx.x & 31;
    float* p = a + (size_t)row * (NH_*NL_*NP_) + h * (NL_*NP_);
    float v0 = p[lane];
    float v1 = p[lane + 32];
    float v2 = (lane < 16) ? p[lane + 64] : -1e30f;
    float mx = fmaxf(v0, fmaxf(v1, v2));
    #pragma unroll
    for (int o = 16; o > 0; o >>= 1) mx = fmaxf(mx, __shfl_xor_sync(0xffffffffu, mx, o));
    float e0 = expf(v0 - mx);
    float e1 = expf(v1 - mx);
    float e2 = (lane < 16) ? expf(v2 - mx) : 0.f;
    float s = e0 + e1 + e2;
    #pragma unroll
    for (int o = 16; o > 0; o >>= 1) s += __shfl_xor_sync(0xffffffffu, s, o);
    float inv = 1.f / s;
    p[lane]      = e0 * inv;
    p[lane + 32] = e1 * inv;
    if (lane < 16) p[lane + 64] = e2 * inv;
}

// ---------------------------------------------------------------------------
// Deformable sampling: one block per token, one warp per head, lane = HD chan.
// acc over 5 levels x 16 points x 4 bilinear corners, attn weight folded in.
// ---------------------------------------------------------------------------
__global__ void sample_kernel(const float* __restrict__ ref)
{
    int r    = blockIdx.x;        // token index in [0, M_)
    int h    = threadIdx.x >> 5;  // head
    int lane = threadIdx.x & 31;  // HD channel
    int b    = r / LQ_;

    __shared__ float s_aw[NH_][NL_*NP_];
    const float* awp = g_attn + (size_t)r * (NH_*NL_*NP_) + h * (NL_*NP_);
    for (int i = lane; i < NL_*NP_; i += 32) s_aw[h][i] = awp[i];
    __syncwarp();

    const float* offp = g_off + (size_t)r * (NH_*NL_*NP_*2) + h * (NL_*NP_*2);
    const float* refp = ref + (size_t)r * (NL_*2);
    const float* valb = g_val + (size_t)b * LQ_ * C_;

    float acc = 0.f;
    #pragma unroll
    for (int l = 0; l < NL_; l++) {
        float rx = refp[l*2 + 0] * (float)W_;
        float ry = refp[l*2 + 1] * (float)H_;
        const float* vlev = valb + (size_t)l * HW_ * C_;
        #pragma unroll 4
        for (int p = 0; p < NP_; p++) {
            float ox = offp[l*NP_*2 + p*2 + 0];
            float oy = offp[l*NP_*2 + p*2 + 1];
            float px = rx + ox - 0.5f;
            float py = ry + oy - 0.5f;
            float x0 = floorf(px), y0 = floorf(py);
            float fx = px - x0,    fy = py - y0;
            int x0i = (int)x0, y0i = (int)y0;
            float aw  = s_aw[h][l*NP_ + p];
            float w00 = aw * (1.f-fy) * (1.f-fx);
            float w01 = aw * (1.f-fy) * fx;
            float w10 = aw * fy * (1.f-fx);
            float w11 = aw * fy * fx;
            int x1i = x0i + 1, y1i = y0i + 1;
            bool vx0 = ((unsigned)x0i < (unsigned)W_);
            bool vx1 = ((unsigned)x1i < (unsigned)W_);
            bool vy0 = ((unsigned)y0i < (unsigned)H_);
            bool vy1 = ((unsigned)y1i < (unsigned)H_);
            int ch = h*HD_ + lane;
            if (vy0 & vx0) acc += w00 * vlev[(size_t)(y0i*W_ + x0i)*C_ + ch];
            if (vy0 & vx1) acc += w01 * vlev[(size_t)(y0i*W_ + x1i)*C_ + ch];
            if (vy1 & vx0) acc += w10 * vlev[(size_t)(y1i*W_ + x0i)*C_ + ch];
            if (vy1 & vx1) acc += w11 * vlev[(size_t)(y1i*W_ + x1i)*C_ + ch];
        }
    }
    g_samp[(size_t)r*C_ + h*HD_ + lane] = acc;
}

// ---------------------------------------------------------------------------
// Launch
// ---------------------------------------------------------------------------
extern "C" void kernel_launch(void* const* d_in, const int* in_sizes, int n_in,
                              void* d_out, int out_size)
{
    const float* x     = (const float*)d_in[0];
    const float* ref   = (const float*)d_in[1];
    const float* n3g   = (const float*)d_in[4];
    const float* n3b   = (const float*)d_in[5];
    const float* n4g   = (const float*)d_in[6];
    const float* n4b   = (const float*)d_in[7];
    const float* w_off = (const float*)d_in[8];
    const float* b_off = (const float*)d_in[9];
    const float* w_attn= (const float*)d_in[10];
    const float* b_attn= (const float*)d_in[11];
    const float* w_val = (const float*)d_in[12];
    const float* b_val = (const float*)d_in[13];
    const float* w_out = (const float*)d_in[14];
    const float* b_out = (const float*)d_in[15];
    const float* w_fc1 = (const float*)d_in[16];
    const float* b_fc1 = (const float*)d_in[17];
    const float* w_fc2 = (const float*)d_in[18];
    const float* b_fc2 = (const float*)d_in[19];
    float* out = (float*)d_out;

    float *p_q, *p_val, *p_off, *p_attn, *p_samp, *p_h, *p_mlp;
    cudaGetSymbolAddress((void**)&p_q,    g_q);
    cudaGetSymbolAddress((void**)&p_val,  g_val);
    cudaGetSymbolAddress((void**)&p_off,  g_off);
    cudaGetSymbolAddress((void**)&p_attn, g_attn);
    cudaGetSymbolAddress((void**)&p_samp, g_samp);
    cudaGetSymbolAddress((void**)&p_h,    g_h);
    cudaGetSymbolAddress((void**)&p_mlp,  g_mlp);

    // 1) LN3: x -> q
    ln_kernel<<<M_, 256>>>(x, n3g, n3b, p_q);

    // 2-4) projections from q
    {
        dim3 gv(C_/128, M_/128);                 // N=256
        sgemm_kernel<0,0><<<gv, 256>>>(M_, C_, C_, p_q, w_val, b_val, nullptr, p_val);
        dim3 go((NH_*NL_*NP_*2)/128, M_/128);    // N=1280
        sgemm_kernel<0,0><<<go, 256>>>(M_, NH_*NL_*NP_*2, C_, p_q, w_off, b_off, nullptr, p_off);
        dim3 ga((NH_*NL_*NP_)/128, M_/128);      // N=640
        sgemm_kernel<0,0><<<ga, 256>>>(M_, NH_*NL_*NP_, C_, p_q, w_attn, b_attn, nullptr, p_attn);
    }

    // 5) softmax over 80 per (token, head)
    softmax_kernel<<<M_, 256>>>(p_attn);

    // 6) deformable bilinear sampling -> g_samp
    sample_kernel<<<M_, 256>>>(ref);

    // 7) out projection + residual(x) -> d_out   (x2 = x + attn)
    {
        dim3 g(C_/128, M_/128);
        sgemm_kernel<0,1><<<g, 256>>>(M_, C_, C_, p_samp, w_out, b_out, x, out);
    }

    // 8) LN4: d_out -> h
    ln_kernel<<<M_, 256>>>(out, n4g, n4b, p_h);

    // 9) fc1 + exact GELU -> g_mlp
    {
        dim3 g(MLP_H_/128, M_/128);
        sgemm_kernel<1,0><<<g, 256>>>(M_, MLP_H_, C_, p_h, w_fc1, b_fc1, nullptr, p_mlp);
    }

    // 10) fc2 + residual(d_out) -> d_out (in place, elementwise-safe)
    {
        dim3 g(C_/128, M_/128);
        sgemm_kernel<0,1><<<g, 256>>>(M_, C_, MLP_H_, p_mlp, w_fc2, b_fc2, out, out);
    }
}

// round 3
// speedup vs baseline: 2.1205x; 2.1205x over previous
#include <cuda_runtime.h>
#include <cuda_bf16.h>
#include <math.h>
#include <stdint.h>

// Problem constants
#define B_    2
#define D_    5
#define H_    32
#define W_    32
#define C_    256
#define NH_   8
#define NL_   5
#define NP_   16
#define HD_   32
#define HW_   (H_*W_)          // 1024
#define LQ_   (D_*HW_)         // 5120
#define M_    (B_*LQ_)         // 10240
#define MLP_H_ 1024

// ---------------- scratch (device globals; no allocation) ----------------
__device__ __nv_bfloat16 g_q   [M_*C_];            // LN3 out (bf16)
__device__ __nv_bfloat16 g_val [M_*C_];            // value projection (bf16)
__device__ float         g_off [M_*NH_*NL_*NP_*2]; // offsets fp32
__device__ float         g_attn[M_*NH_*NL_*NP_];   // attn logits/softmax fp32
__device__ __nv_bfloat16 g_samp[M_*C_];            // sampled attn (bf16)
__device__ __nv_bfloat16 g_h   [M_*C_];            // LN4 out (bf16)
__device__ __nv_bfloat16 g_mlp [M_*MLP_H_];        // fc1+GELU (bf16)
// transposed bf16 weights [N,K]
__device__ __nv_bfloat16 g_wval [C_*C_];
__device__ __nv_bfloat16 g_woff [(NH_*NL_*NP_*2)*C_];
__device__ __nv_bfloat16 g_wattn[(NH_*NL_*NP_)*C_];
__device__ __nv_bfloat16 g_wout [C_*C_];
__device__ __nv_bfloat16 g_wfc1 [MLP_H_*C_];
__device__ __nv_bfloat16 g_wfc2 [C_*MLP_H_];

__device__ __forceinline__ uint32_t smem_u32(const void* p) {
    uint32_t a;
    asm("{ .reg .u64 t; cvta.to.shared.u64 t, %1; cvt.u32.u64 %0, t; }" : "=r"(a) : "l"(p));
    return a;
}
__device__ __forceinline__ void cp_async16(uint32_t s, const void* g) {
    asm volatile("cp.async.cg.shared.global [%0], [%1], 16;" :: "r"(s), "l"(g) : "memory");
}
__device__ __forceinline__ void cp_commit() {
    asm volatile("cp.async.commit_group;" ::: "memory");
}
__device__ __forceinline__ void cp_wait1() {
    asm volatile("cp.async.wait_group 1;" ::: "memory");
}
__device__ __forceinline__ void ldmx4(uint32_t& r0, uint32_t& r1, uint32_t& r2, uint32_t& r3, uint32_t a) {
    asm volatile("ldmatrix.sync.aligned.m8n8.x4.shared.b16 {%0,%1,%2,%3}, [%4];"
                 : "=r"(r0), "=r"(r1), "=r"(r2), "=r"(r3) : "r"(a));
}
__device__ __forceinline__ void ldmx2(uint32_t& r0, uint32_t& r1, uint32_t a) {
    asm volatile("ldmatrix.sync.aligned.m8n8.x2.shared.b16 {%0,%1}, [%2];"
                 : "=r"(r0), "=r"(r1) : "r"(a));
}
__device__ __forceinline__ void mma_bf16(float* c, const uint32_t* a, const uint32_t* b) {
    asm volatile(
        "mma.sync.aligned.m16n8k16.row.col.f32.bf16.bf16.f32 "
        "{%0,%1,%2,%3}, {%4,%5,%6,%7}, {%8,%9}, {%0,%1,%2,%3};"
        : "+f"(c[0]), "+f"(c[1]), "+f"(c[2]), "+f"(c[3])
        : "r"(a[0]), "r"(a[1]), "r"(a[2]), "r"(a[3]), "r"(b[0]), "r"(b[1]));
}

// ---------------------------------------------------------------------------
// LayerNorm: block(256) per row, writes bf16
// ---------------------------------------------------------------------------
__global__ void ln_kernel(const float* __restrict__ x,
                          const float* __restrict__ g,
                          const float* __restrict__ b,
                          __nv_bfloat16* __restrict__ out)
{
    int row = blockIdx.x;
    int c   = threadIdx.x;
    float v = x[(size_t)row*C_ + c];
    float sum = v, sq = v*v;
    #pragma unroll
    for (int o = 16; o > 0; o >>= 1) {
        sum += __shfl_xor_sync(0xffffffffu, sum, o);
        sq  += __shfl_xor_sync(0xffffffffu, sq , o);
    }
    __shared__ float s1[8], s2[8];
    int w = c >> 5, l = c & 31;
    if (l == 0) { s1[w] = sum; s2[w] = sq; }
    __syncthreads();
    sum = 0.f; sq = 0.f;
    #pragma unroll
    for (int i = 0; i < 8; i++) { sum += s1[i]; sq += s2[i]; }
    float m   = sum * (1.f / C_);
    float var = sq  * (1.f / C_) - m*m;
    float inv = rsqrtf(var + 1e-5f);
    out[(size_t)row*C_ + c] = __float2bfloat16((v - m) * inv * g[c] + b[c]);
}

// ---------------------------------------------------------------------------
// Weight transpose+convert: in [K,N] fp32 -> out [N,K] bf16
// ---------------------------------------------------------------------------
__global__ void tcvt_kernel(const float* __restrict__ in,
                            __nv_bfloat16* __restrict__ out, int K, int N)
{
    __shared__ float t[32][33];
    int k = blockIdx.y*32 + threadIdx.y;
    int n = blockIdx.x*32 + threadIdx.x;
    t[threadIdx.y][threadIdx.x] = in[(size_t)k*N + n];
    __syncthreads();
    int on = blockIdx.x*32 + threadIdx.y;
    int ok = blockIdx.y*32 + threadIdx.x;
    out[(size_t)on*K + ok] = __float2bfloat16(t[threadIdx.x][threadIdx.y]);
}

// ---------------------------------------------------------------------------
// HMMA bf16 GEMM: C[M,N] = A[M,K](bf16,[M,K]) @ B(bf16,[N,K])^T + bias
// 128x128 block tile, BK=32, 256 threads (8 warps, each 32x64).
// Double-buffered cp.async. ACT 1 = exact GELU. RES = add fp32 residual.
// ---------------------------------------------------------------------------
#define BK_ 32
#define LDS_ 40   // padded row stride (elements)

template<int ACT, int RES, int BF16OUT>
__global__ void __launch_bounds__(256) gemm_hmma(
    int M, int N, int K,
    const __nv_bfloat16* __restrict__ A,
    const __nv_bfloat16* __restrict__ Bw,
    const float* __restrict__ bias,
    const float* __restrict__ res,
    float* __restrict__ Cf,
    __nv_bfloat16* __restrict__ Cb)
{
    __shared__ __nv_bfloat16 As[2][128][LDS_];
    __shared__ __nv_bfloat16 Bs[2][128][LDS_];

    int tid  = threadIdx.x;
    int lane = tid & 31;
    int wid  = tid >> 5;
    int wm   = wid & 3;     // 4 warps along M (32 rows each)
    int wn   = wid >> 2;    // 2 warps along N (64 cols each)

    int brow = blockIdx.y * 128;
    int bcol = blockIdx.x * 128;
    const int NIT = K / BK_;

    // load mapping: 512 chunks of 16B per tile; thread t handles chunks t, t+256
    int r0c = tid >> 2;            // row of chunk t   (chunk = row*4 + col16)
    int c0c = (tid & 3) * 8;       // element col of 16B chunk
    // chunk t+256: row r0c+64, same col

    auto load_tile = [&](int it, int buf) {
        const __nv_bfloat16* ag = A  + (size_t)(brow + r0c) * K + it*BK_ + c0c;
        cp_async16(smem_u32(&As[buf][r0c][c0c]),      ag);
        cp_async16(smem_u32(&As[buf][r0c+64][c0c]),   ag + (size_t)64*K);
        const __nv_bfloat16* bg = Bw + (size_t)(bcol + r0c) * K + it*BK_ + c0c;
        cp_async16(smem_u32(&Bs[buf][r0c][c0c]),      bg);
        cp_async16(smem_u32(&Bs[buf][r0c+64][c0c]),   bg + (size_t)64*K);
    };

    float acc[2][8][4];
    #pragma unroll
    for (int mi = 0; mi < 2; mi++)
        #pragma unroll
        for (int ni = 0; ni < 8; ni++)
            #pragma unroll
            for (int k = 0; k < 4; k++) acc[mi][ni][k] = 0.f;

    load_tile(0, 0); cp_commit();
    load_tile(1, 1); cp_commit();

    for (int it = 0; it < NIT; ++it) {
        cp_wait1();
        __syncthreads();
        int cur = it & 1;

        #pragma unroll
        for (int kk = 0; kk < 2; kk++) {
            int k0 = kk * 16;
            uint32_t af[2][4], bf[8][2];
            #pragma unroll
            for (int mi = 0; mi < 2; mi++) {
                uint32_t addr = smem_u32(&As[cur][wm*32 + mi*16 + (lane & 15)]
                                                [k0 + (lane >> 4) * 8]);
                ldmx4(af[mi][0], af[mi][1], af[mi][2], af[mi][3], addr);
            }
            #pragma unroll
            for (int ni = 0; ni < 8; ni++) {
                uint32_t addr = smem_u32(&Bs[cur][wn*64 + ni*8 + (lane & 7)]
                                                [k0 + ((lane >> 3) & 1) * 8]);
                ldmx2(bf[ni][0], bf[ni][1], addr);
            }
            #pragma unroll
            for (int mi = 0; mi < 2; mi++)
                #pragma unroll
                for (int ni = 0; ni < 8; ni++)
                    mma_bf16(acc[mi][ni], af[mi], bf[ni]);
        }
        __syncthreads();
        if (it + 2 < NIT) load_tile(it + 2, cur);
        cp_commit();
    }

    // epilogue: fragment layout c0:(g,2t) c1:(g,2t+1) c2:(g+8,2t) c3:(g+8,2t+1)
    int gq = lane >> 2, tq = lane & 3;
    #pragma unroll
    for (int mi = 0; mi < 2; mi++) {
        #pragma unroll
        for (int half = 0; half < 2; half++) {
            int row = brow + wm*32 + mi*16 + half*8 + gq;
            #pragma unroll
            for (int ni = 0; ni < 8; ni++) {
                int col = bcol + wn*64 + ni*8 + tq*2;
                float v0 = acc[mi][ni][half*2 + 0] + bias[col];
                float v1 = acc[mi][ni][half*2 + 1] + bias[col + 1];
                if (ACT == 1) {
                    v0 = 0.5f * v0 * (1.f + erff(v0 * 0.70710678118654752f));
                    v1 = 0.5f * v1 * (1.f + erff(v1 * 0.70710678118654752f));
                }
                if (RES) {
                    const float2 r2 = *(const float2*)&res[(size_t)row * N + col];
                    v0 += r2.x; v1 += r2.y;
                }
                if (BF16OUT) {
                    __nv_bfloat162 o;
                    o.x = __float2bfloat16(v0);
                    o.y = __float2bfloat16(v1);
                    *(__nv_bfloat162*)&Cb[(size_t)row * N + col] = o;
                } else {
                    float2 o; o.x = v0; o.y = v1;
                    *(float2*)&Cf[(size_t)row * N + col] = o;
                }
            }
        }
    }
}

// ---------------------------------------------------------------------------
// Softmax over 80 logits per (token, head). 8 warps = 8 heads.
// ---------------------------------------------------------------------------
__global__ void softmax_kernel(float* __restrict__ a)
{
    int row  = blockIdx.x;
    int h    = threadIdx.x >> 5;
    int lane = threadIdx.x & 31;
    float* p = a + (size_t)row * (NH_*NL_*NP_) + h * (NL_*NP_);
    float v0 = p[lane];
    float v1 = p[lane + 32];
    float v2 = (lane < 16) ? p[lane + 64] : -1e30f;
    float mx = fmaxf(v0, fmaxf(v1, v2));
    #pragma unroll
    for (int o = 16; o > 0; o >>= 1) mx = fmaxf(mx, __shfl_xor_sync(0xffffffffu, mx, o));
    float e0 = expf(v0 - mx);
    float e1 = expf(v1 - mx);
    float e2 = (lane < 16) ? expf(v2 - mx) : 0.f;
    float s = e0 + e1 + e2;
    #pragma unroll
    for (int o = 16; o > 0; o >>= 1) s += __shfl_xor_sync(0xffffffffu, s, o);
    float inv = 1.f / s;
    p[lane]      = e0 * inv;
    p[lane + 32] = e1 * inv;
    if (lane < 16) p[lane + 64] = e2 * inv;
}

// ---------------------------------------------------------------------------
// Deformable sampling: block per token, warp per head, lane = HD channel.
// Value tensor bf16. Output bf16.
// ---------------------------------------------------------------------------
__global__ void sample_kernel(const float* __restrict__ ref)
{
    int r    = blockIdx.x;
    int h    = threadIdx.x >> 5;
    int lane = threadIdx.x & 31;
    int b    = r / LQ_;

    __shared__ float s_aw[NH_][NL_*NP_];
    const float* awp = g_attn + (size_t)r * (NH_*NL_*NP_) + h * (NL_*NP_);
    for (int i = lane; i < NL_*NP_; i += 32) s_aw[h][i] = awp[i];
    __syncwarp();

    const float2* offp = (const float2*)(g_off + (size_t)r * (NH_*NL_*NP_*2) + h * (NL_*NP_*2));
    const float* refp = ref + (size_t)r * (NL_*2);
    const __nv_bfloat16* valb = g_val + (size_t)b * LQ_ * C_;
    int ch = h*HD_ + lane;

    float acc = 0.f;
    #pragma unroll
    for (int l = 0; l < NL_; l++) {
        float rx = refp[l*2 + 0] * (float)W_;
        float ry = refp[l*2 + 1] * (float)H_;
        const __nv_bfloat16* vlev = valb + (size_t)l * HW_ * C_ + ch;
        #pragma unroll 4
        for (int p = 0; p < NP_; p++) {
            float2 o2 = offp[l*NP_ + p];
            float px = rx + o2.x - 0.5f;
            float py = ry + o2.y - 0.5f;
            float x0 = floorf(px), y0 = floorf(py);
            float fx = px - x0,    fy = py - y0;
            int x0i = (int)x0, y0i = (int)y0;
            float aw  = s_aw[h][l*NP_ + p];
            float w00 = aw * (1.f-fy) * (1.f-fx);
            float w01 = aw * (1.f-fy) * fx;
            float w10 = aw * fy * (1.f-fx);
            float w11 = aw * fy * fx;
            int x1i = x0i + 1, y1i = y0i + 1;
            bool vx0 = ((unsigned)x0i < (unsigned)W_);
            bool vx1 = ((unsigned)x1i < (unsigned)W_);
            bool vy0 = ((unsigned)y0i < (unsigned)H_);
            bool vy1 = ((unsigned)y1i < (unsigned)H_);
            if (vy0 & vx0) acc += w00 * __bfloat162float(vlev[(size_t)(y0i*W_ + x0i)*C_]);
            if (vy0 & vx1) acc += w01 * __bfloat162float(vlev[(size_t)(y0i*W_ + x1i)*C_]);
            if (vy1 & vx0) acc += w10 * __bfloat162float(vlev[(size_t)(y1i*W_ + x0i)*C_]);
            if (vy1 & vx1) acc += w11 * __bfloat162float(vlev[(size_t)(y1i*W_ + x1i)*C_]);
        }
    }
    g_samp[(size_t)r*C_ + ch] = __float2bfloat16(acc);
}

// ---------------------------------------------------------------------------
// Launch
// ---------------------------------------------------------------------------
extern "C" void kernel_launch(void* const* d_in, const int* in_sizes, int n_in,
                              void* d_out, int out_size)
{
    const float* x     = (const float*)d_in[0];
    const float* ref   = (const float*)d_in[1];
    const float* n3g   = (const float*)d_in[4];
    const float* n3b   = (const float*)d_in[5];
    const float* n4g   = (const float*)d_in[6];
    const float* n4b   = (const float*)d_in[7];
    const float* w_off = (const float*)d_in[8];
    const float* b_off = (const float*)d_in[9];
    const float* w_attn= (const float*)d_in[10];
    const float* b_attn= (const float*)d_in[11];
    const float* w_val = (const float*)d_in[12];
    const float* b_val = (const float*)d_in[13];
    const float* w_out = (const float*)d_in[14];
    const float* b_out = (const float*)d_in[15];
    const float* w_fc1 = (const float*)d_in[16];
    const float* b_fc1 = (const float*)d_in[17];
    const float* w_fc2 = (const float*)d_in[18];
    const float* b_fc2 = (const float*)d_in[19];
    float* out = (float*)d_out;

    __nv_bfloat16 *p_q, *p_val, *p_samp, *p_h, *p_mlp;
    __nv_bfloat16 *p_wval, *p_woff, *p_wattn, *p_wout, *p_wfc1, *p_wfc2;
    float *p_off, *p_attn;
    cudaGetSymbolAddress((void**)&p_q,    g_q);
    cudaGetSymbolAddress((void**)&p_val,  g_val);
    cudaGetSymbolAddress((void**)&p_off,  g_off);
    cudaGetSymbolAddress((void**)&p_attn, g_attn);
    cudaGetSymbolAddress((void**)&p_samp, g_samp);
    cudaGetSymbolAddress((void**)&p_h,    g_h);
    cudaGetSymbolAddress((void**)&p_mlp,  g_mlp);
    cudaGetSymbolAddress((void**)&p_wval, g_wval);
    cudaGetSymbolAddress((void**)&p_woff, g_woff);
    cudaGetSymbolAddress((void**)&p_wattn,g_wattn);
    cudaGetSymbolAddress((void**)&p_wout, g_wout);
    cudaGetSymbolAddress((void**)&p_wfc1, g_wfc1);
    cudaGetSymbolAddress((void**)&p_wfc2, g_wfc2);

    const int NOFF = NH_*NL_*NP_*2;   // 1280
    const int NATT = NH_*NL_*NP_;     // 640

    // weight transpose+convert (K x N fp32 -> N x K bf16)
    tcvt_kernel<<<dim3(C_/32,    C_/32),    dim3(32,32)>>>(w_val,  p_wval,  C_, C_);
    tcvt_kernel<<<dim3(NOFF/32,  C_/32),    dim3(32,32)>>>(w_off,  p_woff,  C_, NOFF);
    tcvt_kernel<<<dim3(NATT/32,  C_/32),    dim3(32,32)>>>(w_attn, p_wattn, C_, NATT);
    tcvt_kernel<<<dim3(C_/32,    C_/32),    dim3(32,32)>>>(w_out,  p_wout,  C_, C_);
    tcvt_kernel<<<dim3(MLP_H_/32,C_/32),    dim3(32,32)>>>(w_fc1,  p_wfc1,  C_, MLP_H_);
    tcvt_kernel<<<dim3(C_/32,    MLP_H_/32),dim3(32,32)>>>(w_fc2,  p_wfc2,  MLP_H_, C_);

    // 1) LN3 -> q (bf16)
    ln_kernel<<<M_, 256>>>(x, n3g, n3b, p_q);

    // 2) val projection -> bf16
    gemm_hmma<0,0,1><<<dim3(C_/128, M_/128), 256>>>(
        M_, C_, C_, p_q, p_wval, b_val, nullptr, nullptr, p_val);
    // 3) offsets -> fp32
    gemm_hmma<0,0,0><<<dim3(NOFF/128, M_/128), 256>>>(
        M_, NOFF, C_, p_q, p_woff, b_off, nullptr, p_off, nullptr);
    // 4) attn logits -> fp32
    gemm_hmma<0,0,0><<<dim3(NATT/128, M_/128), 256>>>(
        M_, NATT, C_, p_q, p_wattn, b_attn, nullptr, p_attn, nullptr);

    // 5) softmax
    softmax_kernel<<<M_, 256>>>(p_attn);

    // 6) deformable sampling -> bf16
    sample_kernel<<<M_, 256>>>(ref);

    // 7) out projection + residual(x) -> d_out (fp32)
    gemm_hmma<0,1,0><<<dim3(C_/128, M_/128), 256>>>(
        M_, C_, C_, p_samp, p_wout, b_out, x, out, nullptr);

    // 8) LN4 -> h (bf16)
    ln_kernel<<<M_, 256>>>(out, n4g, n4b, p_h);

    // 9) fc1 + GELU -> bf16
    gemm_hmma<1,0,1><<<dim3(MLP_H_/128, M_/128), 256>>>(
        M_, MLP_H_, C_, p_h, p_wfc1, b_fc1, nullptr, nullptr, p_mlp);

    // 10) fc2 + residual(d_out) -> d_out (fp32, in-place elementwise-safe)
    gemm_hmma<0,1,0><<<dim3(C_/128, M_/128), 256>>>(
        M_, C_, MLP_H_, p_mlp, p_wfc2, b_fc2, out, out, nullptr);
}

// round 4
// speedup vs baseline: 3.3958x; 1.6015x over previous
#include <cuda_runtime.h>
#include <cuda_bf16.h>
#include <cuda_fp16.h>
#include <math.h>
#include <stdint.h>

// Problem constants
#define B_    2
#define D_    5
#define H_    32
#define W_    32
#define C_    256
#define NH_   8
#define NL_   5
#define NP_   16
#define HD_   32
#define HW_   (H_*W_)          // 1024
#define LQ_   (D_*HW_)         // 5120
#define M_    (B_*LQ_)         // 10240
#define MLP_H_ 1024
#define PTS_  (NL_*NP_)        // 80

// ---------------- scratch (device globals; no allocation) ----------------
__device__ __nv_bfloat16 g_q   [M_*C_];            // LN3 out (bf16)
__device__ __nv_bfloat16 g_val [M_*C_];            // value projection (bf16)
__device__ float         g_off [M_*NH_*PTS_*2];    // offsets fp32
__device__ float         g_attn[M_*NH_*PTS_];      // attn logits fp32
__device__ uint4         g_rec [(size_t)M_*NH_*PTS_]; // packed sample records
__device__ __nv_bfloat16 g_samp[M_*C_];            // sampled attn (bf16)
__device__ __nv_bfloat16 g_h   [M_*C_];            // LN4 out (bf16)
__device__ __nv_bfloat16 g_mlp [M_*MLP_H_];        // fc1+GELU (bf16)
// transposed bf16 weights [N,K]
__device__ __nv_bfloat16 g_wval [C_*C_];
__device__ __nv_bfloat16 g_woff [(NH_*PTS_*2)*C_];
__device__ __nv_bfloat16 g_wattn[(NH_*PTS_)*C_];
__device__ __nv_bfloat16 g_wout [C_*C_];
__device__ __nv_bfloat16 g_wfc1 [MLP_H_*C_];
__device__ __nv_bfloat16 g_wfc2 [C_*MLP_H_];

__device__ __forceinline__ uint32_t smem_u32(const void* p) {
    uint32_t a;
    asm("{ .reg .u64 t; cvta.to.shared.u64 t, %1; cvt.u32.u64 %0, t; }" : "=r"(a) : "l"(p));
    return a;
}
__device__ __forceinline__ void cp_async16(uint32_t s, const void* g) {
    asm volatile("cp.async.cg.shared.global [%0], [%1], 16;" :: "r"(s), "l"(g) : "memory");
}
__device__ __forceinline__ void cp_commit() {
    asm volatile("cp.async.commit_group;" ::: "memory");
}
__device__ __forceinline__ void cp_wait1() {
    asm volatile("cp.async.wait_group 1;" ::: "memory");
}
__device__ __forceinline__ void ldmx4(uint32_t& r0, uint32_t& r1, uint32_t& r2, uint32_t& r3, uint32_t a) {
    asm volatile("ldmatrix.sync.aligned.m8n8.x4.shared.b16 {%0,%1,%2,%3}, [%4];"
                 : "=r"(r0), "=r"(r1), "=r"(r2), "=r"(r3) : "r"(a));
}
__device__ __forceinline__ void ldmx2(uint32_t& r0, uint32_t& r1, uint32_t a) {
    asm volatile("ldmatrix.sync.aligned.m8n8.x2.shared.b16 {%0,%1}, [%2];"
                 : "=r"(r0), "=r"(r1) : "r"(a));
}
__device__ __forceinline__ void mma_bf16(float* c, const uint32_t* a, const uint32_t* b) {
    asm volatile(
        "mma.sync.aligned.m16n8k16.row.col.f32.bf16.bf16.f32 "
        "{%0,%1,%2,%3}, {%4,%5,%6,%7}, {%8,%9}, {%0,%1,%2,%3};"
        : "+f"(c[0]), "+f"(c[1]), "+f"(c[2]), "+f"(c[3])
        : "r"(a[0]), "r"(a[1]), "r"(a[2]), "r"(a[3]), "r"(b[0]), "r"(b[1]));
}

// ---------------------------------------------------------------------------
// LayerNorm: block(256) per row, writes bf16
// ---------------------------------------------------------------------------
__global__ void ln_kernel(const float* __restrict__ x,
                          const float* __restrict__ g,
                          const float* __restrict__ b,
                          __nv_bfloat16* __restrict__ out)
{
    int row = blockIdx.x;
    int c   = threadIdx.x;
    float v = x[(size_t)row*C_ + c];
    float sum = v, sq = v*v;
    #pragma unroll
    for (int o = 16; o > 0; o >>= 1) {
        sum += __shfl_xor_sync(0xffffffffu, sum, o);
        sq  += __shfl_xor_sync(0xffffffffu, sq , o);
    }
    __shared__ float s1[8], s2[8];
    int w = c >> 5, l = c & 31;
    if (l == 0) { s1[w] = sum; s2[w] = sq; }
    __syncthreads();
    sum = 0.f; sq = 0.f;
    #pragma unroll
    for (int i = 0; i < 8; i++) { sum += s1[i]; sq += s2[i]; }
    float m   = sum * (1.f / C_);
    float var = sq  * (1.f / C_) - m*m;
    float inv = rsqrtf(var + 1e-5f);
    out[(size_t)row*C_ + c] = __float2bfloat16((v - m) * inv * g[c] + b[c]);
}

// ---------------------------------------------------------------------------
// Fused weight transpose+convert for all 6 weights (compile-time shape table)
// in [K,N] fp32 -> out [N,K] bf16; one 32x32 tile per block.
// tiles: val 64 | off 320 | attn 160 | out 64 | fc1 256 | fc2 256  (total 1120)
// ---------------------------------------------------------------------------
__global__ void tcvt6_kernel(
    const float* __restrict__ s0, const float* __restrict__ s1,
    const float* __restrict__ s2, const float* __restrict__ s3,
    const float* __restrict__ s4, const float* __restrict__ s5,
    __nv_bfloat16* __restrict__ d0, __nv_bfloat16* __restrict__ d1,
    __nv_bfloat16* __restrict__ d2, __nv_bfloat16* __restrict__ d3,
    __nv_bfloat16* __restrict__ d4, __nv_bfloat16* __restrict__ d5)
{
    int t = blockIdx.x;
    const float* src; __nv_bfloat16* dst; int K, N;
    if      (t < 64)  { src=s0; dst=d0; K=256;  N=256;          }
    else if (t < 384) { src=s1; dst=d1; K=256;  N=1280; t-=64;  }
    else if (t < 544) { src=s2; dst=d2; K=256;  N=640;  t-=384; }
    else if (t < 608) { src=s3; dst=d3; K=256;  N=256;  t-=544; }
    else if (t < 864) { src=s4; dst=d4; K=256;  N=1024; t-=608; }
    else              { src=s5; dst=d5; K=1024; N=256;  t-=864; }
    int bx = t % (N/32), by = t / (N/32);

    __shared__ float tl[32][33];
    int k = by*32 + threadIdx.y;
    int n = bx*32 + threadIdx.x;
    tl[threadIdx.y][threadIdx.x] = src[(size_t)k*N + n];
    __syncthreads();
    int on = bx*32 + threadIdx.y;
    int ok = by*32 + threadIdx.x;
    dst[(size_t)on*K + ok] = __float2bfloat16(tl[threadIdx.x][threadIdx.y]);
}

// ---------------------------------------------------------------------------
// HMMA bf16 GEMM: C[M,N] = A[M,K](bf16,[M,K]) @ B(bf16,[N,K])^T + bias
// 128x128 block tile, BK=32, 256 threads (8 warps, each 32x64).
// Double-buffered cp.async. ACT 1 = exact GELU. RES = add fp32 residual.
// ---------------------------------------------------------------------------
#define BK_ 32
#define LDS_ 40   // padded row stride (elements)

template<int ACT, int RES, int BF16OUT>
__global__ void __launch_bounds__(256) gemm_hmma(
    int M, int N, int K,
    const __nv_bfloat16* __restrict__ A,
    const __nv_bfloat16* __restrict__ Bw,
    const float* __restrict__ bias,
    const float* __restrict__ res,
    float* __restrict__ Cf,
    __nv_bfloat16* __restrict__ Cb)
{
    __shared__ __nv_bfloat16 As[2][128][LDS_];
    __shared__ __nv_bfloat16 Bs[2][128][LDS_];

    int tid  = threadIdx.x;
    int lane = tid & 31;
    int wid  = tid >> 5;
    int wm   = wid & 3;     // 4 warps along M (32 rows each)
    int wn   = wid >> 2;    // 2 warps along N (64 cols each)

    int brow = blockIdx.y * 128;
    int bcol = blockIdx.x * 128;
    const int NIT = K / BK_;

    int r0c = tid >> 2;
    int c0c = (tid & 3) * 8;

    auto load_tile = [&](int it, int buf) {
        const __nv_bfloat16* ag = A  + (size_t)(brow + r0c) * K + it*BK_ + c0c;
        cp_async16(smem_u32(&As[buf][r0c][c0c]),      ag);
        cp_async16(smem_u32(&As[buf][r0c+64][c0c]),   ag + (size_t)64*K);
        const __nv_bfloat16* bg = Bw + (size_t)(bcol + r0c) * K + it*BK_ + c0c;
        cp_async16(smem_u32(&Bs[buf][r0c][c0c]),      bg);
        cp_async16(smem_u32(&Bs[buf][r0c+64][c0c]),   bg + (size_t)64*K);
    };

    float acc[2][8][4];
    #pragma unroll
    for (int mi = 0; mi < 2; mi++)
        #pragma unroll
        for (int ni = 0; ni < 8; ni++)
            #pragma unroll
            for (int k = 0; k < 4; k++) acc[mi][ni][k] = 0.f;

    load_tile(0, 0); cp_commit();
    load_tile(1, 1); cp_commit();

    for (int it = 0; it < NIT; ++it) {
        cp_wait1();
        __syncthreads();
        int cur = it & 1;

        #pragma unroll
        for (int kk = 0; kk < 2; kk++) {
            int k0 = kk * 16;
            uint32_t af[2][4], bf[8][2];
            #pragma unroll
            for (int mi = 0; mi < 2; mi++) {
                uint32_t addr = smem_u32(&As[cur][wm*32 + mi*16 + (lane & 15)]
                                                [k0 + (lane >> 4) * 8]);
                ldmx4(af[mi][0], af[mi][1], af[mi][2], af[mi][3], addr);
            }
            #pragma unroll
            for (int ni = 0; ni < 8; ni++) {
                uint32_t addr = smem_u32(&Bs[cur][wn*64 + ni*8 + (lane & 7)]
                                                [k0 + ((lane >> 3) & 1) * 8]);
                ldmx2(bf[ni][0], bf[ni][1], addr);
            }
            #pragma unroll
            for (int mi = 0; mi < 2; mi++)
                #pragma unroll
                for (int ni = 0; ni < 8; ni++)
                    mma_bf16(acc[mi][ni], af[mi], bf[ni]);
        }
        __syncthreads();
        if (it + 2 < NIT) load_tile(it + 2, cur);
        cp_commit();
    }

    int gq = lane >> 2, tq = lane & 3;
    #pragma unroll
    for (int mi = 0; mi < 2; mi++) {
        #pragma unroll
        for (int half = 0; half < 2; half++) {
            int row = brow + wm*32 + mi*16 + half*8 + gq;
            #pragma unroll
            for (int ni = 0; ni < 8; ni++) {
                int col = bcol + wn*64 + ni*8 + tq*2;
                float v0 = acc[mi][ni][half*2 + 0] + bias[col];
                float v1 = acc[mi][ni][half*2 + 1] + bias[col + 1];
                if (ACT == 1) {
                    v0 = 0.5f * v0 * (1.f + erff(v0 * 0.70710678118654752f));
                    v1 = 0.5f * v1 * (1.f + erff(v1 * 0.70710678118654752f));
                }
                if (RES) {
                    const float2 r2 = *(const float2*)&res[(size_t)row * N + col];
                    v0 += r2.x; v1 += r2.y;
                }
                if (BF16OUT) {
                    __nv_bfloat162 o;
                    o.x = __float2bfloat16(v0);
                    o.y = __float2bfloat16(v1);
                    *(__nv_bfloat162*)&Cb[(size_t)row * N + col] = o;
                } else {
                    float2 o; o.x = v0; o.y = v1;
                    *(float2*)&Cf[(size_t)row * N + col] = o;
                }
            }
        }
    }
}

// ---------------------------------------------------------------------------
// Fused softmax + sample-prep. Block = token, warp = head, lane covers points
// {lane, lane+32, lane+64}. Packs per point: 4 u16 clamped positions +
// 4 fp16 weights (attn prob and validity folded in) -> uint4 record.
// ---------------------------------------------------------------------------
__global__ void softmax_prep_kernel(const float* __restrict__ ref)
{
    int r    = blockIdx.x;
    int h    = threadIdx.x >> 5;
    int lane = threadIdx.x & 31;

    const float* p = g_attn + (size_t)r * (NH_*PTS_) + h * PTS_;
    float v0 = p[lane];
    float v1 = p[lane + 32];
    float v2 = (lane < 16) ? p[lane + 64] : -1e30f;
    float mx = fmaxf(v0, fmaxf(v1, v2));
    #pragma unroll
    for (int o = 16; o > 0; o >>= 1) mx = fmaxf(mx, __shfl_xor_sync(0xffffffffu, mx, o));
    float e0 = expf(v0 - mx);
    float e1 = expf(v1 - mx);
    float e2 = (lane < 16) ? expf(v2 - mx) : 0.f;
    float s = e0 + e1 + e2;
    #pragma unroll
    for (int o = 16; o > 0; o >>= 1) s += __shfl_xor_sync(0xffffffffu, s, o);
    float inv = 1.f / s;
    float prob[3] = { e0 * inv, e1 * inv, e2 * inv };

    const float2* offp = (const float2*)(g_off + (size_t)r * (NH_*PTS_*2) + h * (PTS_*2));
    uint4* recp = g_rec + (size_t)(r*NH_ + h) * PTS_;
    const float* refr = ref + (size_t)r * (NL_*2);

    #pragma unroll
    for (int j = 0; j < 3; j++) {
        int it = lane + j*32;
        if (it < PTS_) {
            int l = it >> 4;
            float2 o2 = offp[it];
            float px = refr[l*2 + 0] * (float)W_ + o2.x - 0.5f;
            float py = refr[l*2 + 1] * (float)H_ + o2.y - 0.5f;
            float x0f = floorf(px), y0f = floorf(py);
            float fx = px - x0f, fy = py - y0f;
            int x0 = (int)x0f, y0 = (int)y0f;
            float aw = prob[j];
            float w00 = aw*(1.f-fy)*(1.f-fx);
            float w01 = aw*(1.f-fy)*fx;
            float w10 = aw*fy*(1.f-fx);
            float w11 = aw*fy*fx;
            if (!(((unsigned)y0     < (unsigned)H_) && ((unsigned)x0     < (unsigned)W_))) w00 = 0.f;
            if (!(((unsigned)y0     < (unsigned)H_) && ((unsigned)(x0+1) < (unsigned)W_))) w01 = 0.f;
            if (!(((unsigned)(y0+1) < (unsigned)H_) && ((unsigned)x0     < (unsigned)W_))) w10 = 0.f;
            if (!(((unsigned)(y0+1) < (unsigned)H_) && ((unsigned)(x0+1) < (unsigned)W_))) w11 = 0.f;
            int xc0 = min(max(x0,     0), W_-1);
            int xc1 = min(max(x0 + 1, 0), W_-1);
            int yc0 = min(max(y0,     0), H_-1);
            int yc1 = min(max(y0 + 1, 0), H_-1);
            uint32_t p00 = (uint32_t)(yc0*W_ + xc0);
            uint32_t p01 = (uint32_t)(yc0*W_ + xc1);
            uint32_t p10 = (uint32_t)(yc1*W_ + xc0);
            uint32_t p11 = (uint32_t)(yc1*W_ + xc1);
            uint4 rec;
            rec.x = p00 | (p01 << 16);
            rec.y = p10 | (p11 << 16);
            __half2 h01 = __floats2half2_rn(w00, w01);
            __half2 h23 = __floats2half2_rn(w10, w11);
            rec.z = *(uint32_t*)&h01;
            rec.w = *(uint32_t*)&h23;
            recp[it] = rec;
        }
    }
}

// ---------------------------------------------------------------------------
// Gather: block = token, warp = head. Lanes 0-15 = channel pairs (bf16x2),
// lane>>4 = point parity -> warp retires 2 points/iter. Cross-half reduce
// via shfl_xor(16); lanes 0-15 store bf16x2.
// ---------------------------------------------------------------------------
__global__ void gather_kernel()
{
    int r    = blockIdx.x;
    int h    = threadIdx.x >> 5;
    int lane = threadIdx.x & 31;
    int c2   = lane & 15;
    int half = lane >> 4;
    int b    = r / LQ_;

    const uint4* recp = g_rec + (size_t)(r*NH_ + h) * PTS_;
    const __nv_bfloat16* vb0 = g_val + (size_t)(b*LQ_)*C_ + h*HD_ + c2*2;

    float a0 = 0.f, a1 = 0.f;
    #pragma unroll 4
    for (int i = 0; i < PTS_/2; i++) {
        int it = 2*i + half;
        uint4 rec = recp[it];
        int l = it >> 4;
        const __nv_bfloat16* vb = vb0 + (size_t)l * HW_ * C_;
        float2 w01 = __half22float2(*(__half2*)&rec.z);
        float2 w23 = __half22float2(*(__half2*)&rec.w);
        uint32_t v;
        v = *(const uint32_t*)(vb + (rec.x & 0xFFFFu) * C_);
        a0 += w01.x * __uint_as_float(v << 16);
        a1 += w01.x * __uint_as_float(v & 0xFFFF0000u);
        v = *(const uint32_t*)(vb + (rec.x >> 16) * C_);
        a0 += w01.y * __uint_as_float(v << 16);
        a1 += w01.y * __uint_as_float(v & 0xFFFF0000u);
        v = *(const uint32_t*)(vb + (rec.y & 0xFFFFu) * C_);
        a0 += w23.x * __uint_as_float(v << 16);
        a1 += w23.x * __uint_as_float(v & 0xFFFF0000u);
        v = *(const uint32_t*)(vb + (rec.y >> 16) * C_);
        a0 += w23.y * __uint_as_float(v << 16);
        a1 += w23.y * __uint_as_float(v & 0xFFFF0000u);
    }
    a0 += __shfl_xor_sync(0xffffffffu, a0, 16);
    a1 += __shfl_xor_sync(0xffffffffu, a1, 16);
    if (half == 0) {
        __nv_bfloat162 o;
        o.x = __float2bfloat16(a0);
        o.y = __float2bfloat16(a1);
        *(__nv_bfloat162*)(g_samp + (size_t)r*C_ + h*HD_ + c2*2) = o;
    }
}

// ---------------------------------------------------------------------------
// Launch
// ---------------------------------------------------------------------------
extern "C" void kernel_launch(void* const* d_in, const int* in_sizes, int n_in,
                              void* d_out, int out_size)
{
    const float* x     = (const float*)d_in[0];
    const float* ref   = (const float*)d_in[1];
    const float* n3g   = (const float*)d_in[4];
    const float* n3b   = (const float*)d_in[5];
    const float* n4g   = (const float*)d_in[6];
    const float* n4b   = (const float*)d_in[7];
    const float* w_off = (const float*)d_in[8];
    const float* b_off = (const float*)d_in[9];
    const float* w_attn= (const float*)d_in[10];
    const float* b_attn= (const float*)d_in[11];
    const float* w_val = (const float*)d_in[12];
    const float* b_val = (const float*)d_in[13];
    const float* w_out = (const float*)d_in[14];
    const float* b_out = (const float*)d_in[15];
    const float* w_fc1 = (const float*)d_in[16];
    const float* b_fc1 = (const float*)d_in[17];
    const float* w_fc2 = (const float*)d_in[18];
    const float* b_fc2 = (const float*)d_in[19];
    float* out = (float*)d_out;

    __nv_bfloat16 *p_q, *p_val, *p_samp, *p_h, *p_mlp;
    __nv_bfloat16 *p_wval, *p_woff, *p_wattn, *p_wout, *p_wfc1, *p_wfc2;
    float *p_off, *p_attn;
    cudaGetSymbolAddress((void**)&p_q,    g_q);
    cudaGetSymbolAddress((void**)&p_val,  g_val);
    cudaGetSymbolAddress((void**)&p_off,  g_off);
    cudaGetSymbolAddress((void**)&p_attn, g_attn);
    cudaGetSymbolAddress((void**)&p_samp, g_samp);
    cudaGetSymbolAddress((void**)&p_h,    g_h);
    cudaGetSymbolAddress((void**)&p_mlp,  g_mlp);
    cudaGetSymbolAddress((void**)&p_wval, g_wval);
    cudaGetSymbolAddress((void**)&p_woff, g_woff);
    cudaGetSymbolAddress((void**)&p_wattn,g_wattn);
    cudaGetSymbolAddress((void**)&p_wout, g_wout);
    cudaGetSymbolAddress((void**)&p_wfc1, g_wfc1);
    cudaGetSymbolAddress((void**)&p_wfc2, g_wfc2);

    const int NOFF = NH_*PTS_*2;   // 1280
    const int NATT = NH_*PTS_;     // 640

    // fused weight transpose+convert (all 6 weights, one launch)
    tcvt6_kernel<<<1120, dim3(32,32)>>>(
        w_val, w_off, w_attn, w_out, w_fc1, w_fc2,
        p_wval, p_woff, p_wattn, p_wout, p_wfc1, p_wfc2);

    // 1) LN3 -> q (bf16)
    ln_kernel<<<M_, 256>>>(x, n3g, n3b, p_q);

    // 2) val projection -> bf16
    gemm_hmma<0,0,1><<<dim3(C_/128, M_/128), 256>>>(
        M_, C_, C_, p_q, p_wval, b_val, nullptr, nullptr, p_val);
    // 3) offsets -> fp32
    gemm_hmma<0,0,0><<<dim3(NOFF/128, M_/128), 256>>>(
        M_, NOFF, C_, p_q, p_woff, b_off, nullptr, p_off, nullptr);
    // 4) attn logits -> fp32
    gemm_hmma<0,0,0><<<dim3(NATT/128, M_/128), 256>>>(
        M_, NATT, C_, p_q, p_wattn, b_attn, nullptr, p_attn, nullptr);

    // 5) fused softmax + sample prep -> g_rec
    softmax_prep_kernel<<<M_, 256>>>(ref);

    // 6) gather -> g_samp (bf16)
    gather_kernel<<<M_, 256>>>();

    // 7) out projection + residual(x) -> d_out (fp32)
    gemm_hmma<0,1,0><<<dim3(C_/128, M_/128), 256>>>(
        M_, C_, C_, p_samp, p_wout, b_out, x, out, nullptr);

    // 8) LN4 -> h (bf16)
    ln_kernel<<<M_, 256>>>(out, n4g, n4b, p_h);

    // 9) fc1 + GELU -> bf16
    gemm_hmma<1,0,1><<<dim3(MLP_H_/128, M_/128), 256>>>(
        M_, MLP_H_, C_, p_h, p_wfc1, b_fc1, nullptr, nullptr, p_mlp);

    // 10) fc2 + residual(d_out) -> d_out (fp32, in-place elementwise-safe)
    gemm_hmma<0,1,0><<<dim3(C_/128, M_/128), 256>>>(
        M_, C_, MLP_H_, p_mlp, p_wfc2, b_fc2, out, out, nullptr);
}

// round 5
// speedup vs baseline: 3.4750x; 1.0233x over previous
#include <cuda_runtime.h>
#include <cuda_bf16.h>
#include <cuda_fp16.h>
#include <math.h>
#include <stdint.h>

// Problem constants
#define B_    2
#define D_    5
#define H_    32
#define W_    32
#define C_    256
#define NH_   8
#define NL_   5
#define NP_   16
#define HD_   32
#define HW_   (H_*W_)          // 1024
#define LQ_   (D_*HW_)         // 5120
#define M_    (B_*LQ_)         // 10240
#define MLP_H_ 1024
#define PTS_  (NL_*NP_)        // 80
#define NPROJ_ 2176            // 256 (val) + 1280 (off) + 640 (attn)
#define LVL_STRIDE_ (NH_*HW_*HD_)   // 262144 elements per level (head-major val)

// ---------------- scratch (device globals; no allocation) ----------------
__device__ __nv_bfloat16 g_q   [M_*C_];            // LN3 out (bf16)
__device__ __nv_bfloat16 g_valh[B_*NL_*NH_*HW_*HD_]; // value, head-major layout
__device__ float         g_off [M_*NH_*PTS_*2];    // offsets fp32
__device__ float         g_attn[M_*NH_*PTS_];      // attn logits fp32
__device__ uint4         g_rec [(size_t)M_*NH_*PTS_]; // packed sample records
__device__ __nv_bfloat16 g_samp[M_*C_];            // sampled attn (bf16)
__device__ __nv_bfloat16 g_h   [M_*C_];            // LN4 out (bf16)
__device__ __nv_bfloat16 g_mlp [M_*MLP_H_];        // fc1+GELU (bf16)
// transposed bf16 weights [N,K]
__device__ __nv_bfloat16 g_wproj[NPROJ_*C_];       // concat: val|off|attn rows
__device__ __nv_bfloat16 g_wout [C_*C_];
__device__ __nv_bfloat16 g_wfc1 [MLP_H_*C_];
__device__ __nv_bfloat16 g_wfc2 [C_*MLP_H_];

__device__ __forceinline__ uint32_t smem_u32(const void* p) {
    uint32_t a;
    asm("{ .reg .u64 t; cvta.to.shared.u64 t, %1; cvt.u32.u64 %0, t; }" : "=r"(a) : "l"(p));
    return a;
}
__device__ __forceinline__ void cp_async16(uint32_t s, const void* g) {
    asm volatile("cp.async.cg.shared.global [%0], [%1], 16;" :: "r"(s), "l"(g) : "memory");
}
__device__ __forceinline__ void cp_commit() {
    asm volatile("cp.async.commit_group;" ::: "memory");
}
__device__ __forceinline__ void cp_wait1() {
    asm volatile("cp.async.wait_group 1;" ::: "memory");
}
__device__ __forceinline__ void ldmx4(uint32_t& r0, uint32_t& r1, uint32_t& r2, uint32_t& r3, uint32_t a) {
    asm volatile("ldmatrix.sync.aligned.m8n8.x4.shared.b16 {%0,%1,%2,%3}, [%4];"
                 : "=r"(r0), "=r"(r1), "=r"(r2), "=r"(r3) : "r"(a));
}
__device__ __forceinline__ void ldmx2(uint32_t& r0, uint32_t& r1, uint32_t a) {
    asm volatile("ldmatrix.sync.aligned.m8n8.x2.shared.b16 {%0,%1}, [%2];"
                 : "=r"(r0), "=r"(r1) : "r"(a));
}
__device__ __forceinline__ void mma_bf16(float* c, const uint32_t* a, const uint32_t* b) {
    asm volatile(
        "mma.sync.aligned.m16n8k16.row.col.f32.bf16.bf16.f32 "
        "{%0,%1,%2,%3}, {%4,%5,%6,%7}, {%8,%9}, {%0,%1,%2,%3};"
        : "+f"(c[0]), "+f"(c[1]), "+f"(c[2]), "+f"(c[3])
        : "r"(a[0]), "r"(a[1]), "r"(a[2]), "r"(a[3]), "r"(b[0]), "r"(b[1]));
}

// ---------------------------------------------------------------------------
// LayerNorm: block(256) per row, writes bf16
// ---------------------------------------------------------------------------
__global__ void ln_kernel(const float* __restrict__ x,
                          const float* __restrict__ g,
                          const float* __restrict__ b,
                          __nv_bfloat16* __restrict__ out)
{
    int row = blockIdx.x;
    int c   = threadIdx.x;
    float v = x[(size_t)row*C_ + c];
    float sum = v, sq = v*v;
    #pragma unroll
    for (int o = 16; o > 0; o >>= 1) {
        sum += __shfl_xor_sync(0xffffffffu, sum, o);
        sq  += __shfl_xor_sync(0xffffffffu, sq , o);
    }
    __shared__ float s1[8], s2[8];
    int w = c >> 5, l = c & 31;
    if (l == 0) { s1[w] = sum; s2[w] = sq; }
    __syncthreads();
    sum = 0.f; sq = 0.f;
    #pragma unroll
    for (int i = 0; i < 8; i++) { sum += s1[i]; sq += s2[i]; }
    float m   = sum * (1.f / C_);
    float var = sq  * (1.f / C_) - m*m;
    float inv = rsqrtf(var + 1e-5f);
    out[(size_t)row*C_ + c] = __float2bfloat16((v - m) * inv * g[c] + b[c]);
}

// ---------------------------------------------------------------------------
// Fused weight transpose+convert: 4 sources -> g_wproj slices + out/fc1/fc2
// in [K,N] fp32 -> out [N,K] bf16; one 32x32 tile per block.
// tiles: val 64 | off 320 | attn 160 | out 64 | fc1 256 | fc2 256 (1120)
// ---------------------------------------------------------------------------
__global__ void tcvt6_kernel(
    const float* __restrict__ s0, const float* __restrict__ s1,
    const float* __restrict__ s2, const float* __restrict__ s3,
    const float* __restrict__ s4, const float* __restrict__ s5,
    __nv_bfloat16* __restrict__ dproj,
    __nv_bfloat16* __restrict__ d3,
    __nv_bfloat16* __restrict__ d4, __nv_bfloat16* __restrict__ d5)
{
    int t = blockIdx.x;
    const float* src; __nv_bfloat16* dst; int K, N;
    if      (t < 64)  { src=s0; dst=dproj;              K=256;  N=256;          }
    else if (t < 384) { src=s1; dst=dproj + 256*256;    K=256;  N=1280; t-=64;  }
    else if (t < 544) { src=s2; dst=dproj + 1536*256;   K=256;  N=640;  t-=384; }
    else if (t < 608) { src=s3; dst=d3;                 K=256;  N=256;  t-=544; }
    else if (t < 864) { src=s4; dst=d4;                 K=256;  N=1024; t-=608; }
    else              { src=s5; dst=d5;                 K=1024; N=256;  t-=864; }
    int bx = t % (N/32), by = t / (N/32);

    __shared__ float tl[32][33];
    int k = by*32 + threadIdx.y;
    int n = bx*32 + threadIdx.x;
    tl[threadIdx.y][threadIdx.x] = src[(size_t)k*N + n];
    __syncthreads();
    int on = bx*32 + threadIdx.y;
    int ok = by*32 + threadIdx.x;
    dst[(size_t)on*K + ok] = __float2bfloat16(tl[threadIdx.x][threadIdx.y]);
}

// ---------------------------------------------------------------------------
// Shared GEMM mainloop macro context: 128x128 tile, BK=32, 256 thr, 8 warps.
// ---------------------------------------------------------------------------
#define BK_ 32
#define LDS_ 40   // padded row stride (elements)

// Generic HMMA GEMM (out/fc1/fc2): + bias, optional GELU, optional residual.
template<int ACT, int RES, int BF16OUT>
__global__ void __launch_bounds__(256) gemm_hmma(
    int M, int N, int K,
    const __nv_bfloat16* __restrict__ A,
    const __nv_bfloat16* __restrict__ Bw,
    const float* __restrict__ bias,
    const float* __restrict__ res,
    float* __restrict__ Cf,
    __nv_bfloat16* __restrict__ Cb)
{
    __shared__ __nv_bfloat16 As[2][128][LDS_];
    __shared__ __nv_bfloat16 Bs[2][128][LDS_];

    int tid  = threadIdx.x;
    int lane = tid & 31;
    int wid  = tid >> 5;
    int wm   = wid & 3;
    int wn   = wid >> 2;

    int brow = blockIdx.y * 128;
    int bcol = blockIdx.x * 128;
    const int NIT = K / BK_;

    int r0c = tid >> 2;
    int c0c = (tid & 3) * 8;

    auto load_tile = [&](int it, int buf) {
        const __nv_bfloat16* ag = A  + (size_t)(brow + r0c) * K + it*BK_ + c0c;
        cp_async16(smem_u32(&As[buf][r0c][c0c]),      ag);
        cp_async16(smem_u32(&As[buf][r0c+64][c0c]),   ag + (size_t)64*K);
        const __nv_bfloat16* bg = Bw + (size_t)(bcol + r0c) * K + it*BK_ + c0c;
        cp_async16(smem_u32(&Bs[buf][r0c][c0c]),      bg);
        cp_async16(smem_u32(&Bs[buf][r0c+64][c0c]),   bg + (size_t)64*K);
    };

    float acc[2][8][4];
    #pragma unroll
    for (int mi = 0; mi < 2; mi++)
        #pragma unroll
        for (int ni = 0; ni < 8; ni++)
            #pragma unroll
            for (int k = 0; k < 4; k++) acc[mi][ni][k] = 0.f;

    load_tile(0, 0); cp_commit();
    load_tile(1, 1); cp_commit();

    for (int it = 0; it < NIT; ++it) {
        cp_wait1();
        __syncthreads();
        int cur = it & 1;

        #pragma unroll
        for (int kk = 0; kk < 2; kk++) {
            int k0 = kk * 16;
            uint32_t af[2][4], bfr[8][2];
            #pragma unroll
            for (int mi = 0; mi < 2; mi++) {
                uint32_t addr = smem_u32(&As[cur][wm*32 + mi*16 + (lane & 15)]
                                                [k0 + (lane >> 4) * 8]);
                ldmx4(af[mi][0], af[mi][1], af[mi][2], af[mi][3], addr);
            }
            #pragma unroll
            for (int ni = 0; ni < 8; ni++) {
                uint32_t addr = smem_u32(&Bs[cur][wn*64 + ni*8 + (lane & 7)]
                                                [k0 + ((lane >> 3) & 1) * 8]);
                ldmx2(bfr[ni][0], bfr[ni][1], addr);
            }
            #pragma unroll
            for (int mi = 0; mi < 2; mi++)
                #pragma unroll
                for (int ni = 0; ni < 8; ni++)
                    mma_bf16(acc[mi][ni], af[mi], bfr[ni]);
        }
        __syncthreads();
        if (it + 2 < NIT) load_tile(it + 2, cur);
        cp_commit();
    }

    int gq = lane >> 2, tq = lane & 3;
    #pragma unroll
    for (int mi = 0; mi < 2; mi++) {
        #pragma unroll
        for (int half = 0; half < 2; half++) {
            int row = brow + wm*32 + mi*16 + half*8 + gq;
            #pragma unroll
            for (int ni = 0; ni < 8; ni++) {
                int col = bcol + wn*64 + ni*8 + tq*2;
                float v0 = acc[mi][ni][half*2 + 0] + bias[col];
                float v1 = acc[mi][ni][half*2 + 1] + bias[col + 1];
                if (ACT == 1) {
                    v0 = 0.5f * v0 * (1.f + erff(v0 * 0.70710678118654752f));
                    v1 = 0.5f * v1 * (1.f + erff(v1 * 0.70710678118654752f));
                }
                if (RES) {
                    const float2 r2 = *(const float2*)&res[(size_t)row * N + col];
                    v0 += r2.x; v1 += r2.y;
                }
                if (BF16OUT) {
                    __nv_bfloat162 o;
                    o.x = __float2bfloat16(v0);
                    o.y = __float2bfloat16(v1);
                    *(__nv_bfloat162*)&Cb[(size_t)row * N + col] = o;
                } else {
                    float2 o; o.x = v0; o.y = v1;
                    *(float2*)&Cf[(size_t)row * N + col] = o;
                }
            }
        }
    }
}

// ---------------------------------------------------------------------------
// Fused projection GEMM: A[M,256] @ Wproj[2176,256]^T. Epilogue routes by
// column region (uniform per block): val -> bf16 head-major g_valh,
// off -> fp32 g_off, attn -> fp32 g_attn.
// ---------------------------------------------------------------------------
__global__ void __launch_bounds__(256) gemm_proj(
    const __nv_bfloat16* __restrict__ A,
    const float* __restrict__ bv,
    const float* __restrict__ bo,
    const float* __restrict__ ba)
{
    const int K = C_;
    __shared__ __nv_bfloat16 As[2][128][LDS_];
    __shared__ __nv_bfloat16 Bs[2][128][LDS_];

    int tid  = threadIdx.x;
    int lane = tid & 31;
    int wid  = tid >> 5;
    int wm   = wid & 3;
    int wn   = wid >> 2;

    int brow = blockIdx.y * 128;
    int bcol = blockIdx.x * 128;
    const int NIT = K / BK_;

    int r0c = tid >> 2;
    int c0c = (tid & 3) * 8;
    const __nv_bfloat16* Bw = g_wproj;

    auto load_tile = [&](int it, int buf) {
        const __nv_bfloat16* ag = A  + (size_t)(brow + r0c) * K + it*BK_ + c0c;
        cp_async16(smem_u32(&As[buf][r0c][c0c]),      ag);
        cp_async16(smem_u32(&As[buf][r0c+64][c0c]),   ag + (size_t)64*K);
        const __nv_bfloat16* bg = Bw + (size_t)(bcol + r0c) * K + it*BK_ + c0c;
        cp_async16(smem_u32(&Bs[buf][r0c][c0c]),      bg);
        cp_async16(smem_u32(&Bs[buf][r0c+64][c0c]),   bg + (size_t)64*K);
    };

    float acc[2][8][4];
    #pragma unroll
    for (int mi = 0; mi < 2; mi++)
        #pragma unroll
        for (int ni = 0; ni < 8; ni++)
            #pragma unroll
            for (int k = 0; k < 4; k++) acc[mi][ni][k] = 0.f;

    load_tile(0, 0); cp_commit();
    load_tile(1, 1); cp_commit();

    for (int it = 0; it < NIT; ++it) {
        cp_wait1();
        __syncthreads();
        int cur = it & 1;
        #pragma unroll
        for (int kk = 0; kk < 2; kk++) {
            int k0 = kk * 16;
            uint32_t af[2][4], bfr[8][2];
            #pragma unroll
            for (int mi = 0; mi < 2; mi++) {
                uint32_t addr = smem_u32(&As[cur][wm*32 + mi*16 + (lane & 15)]
                                                [k0 + (lane >> 4) * 8]);
                ldmx4(af[mi][0], af[mi][1], af[mi][2], af[mi][3], addr);
            }
            #pragma unroll
            for (int ni = 0; ni < 8; ni++) {
                uint32_t addr = smem_u32(&Bs[cur][wn*64 + ni*8 + (lane & 7)]
                                                [k0 + ((lane >> 3) & 1) * 8]);
                ldmx2(bfr[ni][0], bfr[ni][1], addr);
            }
            #pragma unroll
            for (int mi = 0; mi < 2; mi++)
                #pragma unroll
                for (int ni = 0; ni < 8; ni++)
                    mma_bf16(acc[mi][ni], af[mi], bfr[ni]);
        }
        __syncthreads();
        if (it + 2 < NIT) load_tile(it + 2, cur);
        cp_commit();
    }

    int gq = lane >> 2, tq = lane & 3;
    if (bcol < 256) {
        // val region -> bf16 head-major: g_valh[((b*5+d)*8+h)*1024 + pix][32]
        #pragma unroll
        for (int mi = 0; mi < 2; mi++)
            #pragma unroll
            for (int half = 0; half < 2; half++) {
                int row = brow + wm*32 + mi*16 + half*8 + gq;
                int bb  = row / LQ_;
                int rem = row - bb*LQ_;
                int d   = rem >> 10;
                int pix = rem & 1023;
                size_t tokbase = ((size_t)((bb*NL_ + d)*NH_) * HW_ + pix) * HD_;
                #pragma unroll
                for (int ni = 0; ni < 8; ni++) {
                    int col = bcol + wn*64 + ni*8 + tq*2;
                    int h  = col >> 5;
                    int hd = col & 31;
                    float v0 = acc[mi][ni][half*2 + 0] + bv[col];
                    float v1 = acc[mi][ni][half*2 + 1] + bv[col + 1];
                    __nv_bfloat162 o;
                    o.x = __float2bfloat16(v0);
                    o.y = __float2bfloat16(v1);
                    *(__nv_bfloat162*)&g_valh[tokbase + (size_t)h*HW_*HD_ + hd] = o;
                }
            }
    } else if (bcol < 1536) {
        #pragma unroll
        for (int mi = 0; mi < 2; mi++)
            #pragma unroll
            for (int half = 0; half < 2; half++) {
                int row = brow + wm*32 + mi*16 + half*8 + gq;
                #pragma unroll
                for (int ni = 0; ni < 8; ni++) {
                    int col = bcol - 256 + wn*64 + ni*8 + tq*2;
                    float2 o;
                    o.x = acc[mi][ni][half*2 + 0] + bo[col];
                    o.y = acc[mi][ni][half*2 + 1] + bo[col + 1];
                    *(float2*)&g_off[(size_t)row * 1280 + col] = o;
                }
            }
    } else {
        #pragma unroll
        for (int mi = 0; mi < 2; mi++)
            #pragma unroll
            for (int half = 0; half < 2; half++) {
                int row = brow + wm*32 + mi*16 + half*8 + gq;
                #pragma unroll
                for (int ni = 0; ni < 8; ni++) {
                    int col = bcol - 1536 + wn*64 + ni*8 + tq*2;
                    float2 o;
                    o.x = acc[mi][ni][half*2 + 0] + ba[col];
                    o.y = acc[mi][ni][half*2 + 1] + ba[col + 1];
                    *(float2*)&g_attn[(size_t)row * 640 + col] = o;
                }
            }
    }
}

// ---------------------------------------------------------------------------
// Fused softmax + sample-prep. Block = token, warp = head, lane covers points
// {lane, lane+32, lane+64}. Packs per point: 4 u16 clamped positions +
// 4 fp16 weights (attn prob and validity folded in) -> uint4 record.
// ---------------------------------------------------------------------------
__global__ void softmax_prep_kernel(const float* __restrict__ ref)
{
    int r    = blockIdx.x;
    int h    = threadIdx.x >> 5;
    int lane = threadIdx.x & 31;

    const float* p = g_attn + (size_t)r * (NH_*PTS_) + h * PTS_;
    float v0 = p[lane];
    float v1 = p[lane + 32];
    float v2 = (lane < 16) ? p[lane + 64] : -1e30f;
    float mx = fmaxf(v0, fmaxf(v1, v2));
    #pragma unroll
    for (int o = 16; o > 0; o >>= 1) mx = fmaxf(mx, __shfl_xor_sync(0xffffffffu, mx, o));
    float e0 = expf(v0 - mx);
    float e1 = expf(v1 - mx);
    float e2 = (lane < 16) ? expf(v2 - mx) : 0.f;
    float s = e0 + e1 + e2;
    #pragma unroll
    for (int o = 16; o > 0; o >>= 1) s += __shfl_xor_sync(0xffffffffu, s, o);
    float inv = 1.f / s;
    float prob[3] = { e0 * inv, e1 * inv, e2 * inv };

    const float2* offp = (const float2*)(g_off + (size_t)r * (NH_*PTS_*2) + h * (PTS_*2));
    uint4* recp = g_rec + (size_t)(r*NH_ + h) * PTS_;
    const float* refr = ref + (size_t)r * (NL_*2);

    #pragma unroll
    for (int j = 0; j < 3; j++) {
        int it = lane + j*32;
        if (it < PTS_) {
            int l = it >> 4;
            float2 o2 = offp[it];
            float px = refr[l*2 + 0] * (float)W_ + o2.x - 0.5f;
            float py = refr[l*2 + 1] * (float)H_ + o2.y - 0.5f;
            float x0f = floorf(px), y0f = floorf(py);
            float fx = px - x0f, fy = py - y0f;
            int x0 = (int)x0f, y0 = (int)y0f;
            float aw = prob[j];
            float w00 = aw*(1.f-fy)*(1.f-fx);
            float w01 = aw*(1.f-fy)*fx;
            float w10 = aw*fy*(1.f-fx);
            float w11 = aw*fy*fx;
            if (!(((unsigned)y0     < (unsigned)H_) && ((unsigned)x0     < (unsigned)W_))) w00 = 0.f;
            if (!(((unsigned)y0     < (unsigned)H_) && ((unsigned)(x0+1) < (unsigned)W_))) w01 = 0.f;
            if (!(((unsigned)(y0+1) < (unsigned)H_) && ((unsigned)x0     < (unsigned)W_))) w10 = 0.f;
            if (!(((unsigned)(y0+1) < (unsigned)H_) && ((unsigned)(x0+1) < (unsigned)W_))) w11 = 0.f;
            int xc0 = min(max(x0,     0), W_-1);
            int xc1 = min(max(x0 + 1, 0), W_-1);
            int yc0 = min(max(y0,     0), H_-1);
            int yc1 = min(max(y0 + 1, 0), H_-1);
            uint32_t p00 = (uint32_t)(yc0*W_ + xc0);
            uint32_t p01 = (uint32_t)(yc0*W_ + xc1);
            uint32_t p10 = (uint32_t)(yc1*W_ + xc0);
            uint32_t p11 = (uint32_t)(yc1*W_ + xc1);
            uint4 rec;
            rec.x = p00 | (p01 << 16);
            rec.y = p10 | (p11 << 16);
            __half2 h01 = __floats2half2_rn(w00, w01);
            __half2 h23 = __floats2half2_rn(w10, w11);
            rec.z = *(uint32_t*)&h01;
            rec.w = *(uint32_t*)&h23;
            recp[it] = rec;
        }
    }
}

// ---------------------------------------------------------------------------
// Gather v2: block = token, warp = head. lane = (yrow, xpix, chanquad):
// one LDG.64 per point covers the whole 2x2x32ch footprint (head-major val).
// Cross-corner reduce via shfl_xor(8), shfl_xor(16). Lanes 0-7 store 8B.
// ---------------------------------------------------------------------------
__global__ void gather_kernel()
{
    int r    = blockIdx.x;
    int h    = threadIdx.x >> 5;
    int lane = threadIdx.x & 31;
    int yr   = (lane >> 4) & 1;
    int xp   = (lane >> 3) & 1;
    int cq   = lane & 7;
    int bsh  = xp * 16;
    int b    = r / LQ_;

    const uint4* recp = g_rec + (size_t)(r*NH_ + h) * PTS_;
    const __nv_bfloat16* vb0 = g_valh
        + (size_t)((b*NL_)*NH_ + h) * (HW_*HD_) + cq*4;

    float a0 = 0.f, a1 = 0.f, a2 = 0.f, a3 = 0.f;
    #pragma unroll 4
    for (int i = 0; i < PTS_; i++) {
        uint4 rec = recp[i];
        int l = i >> 4;
        const __nv_bfloat16* vl = vb0 + (size_t)l * LVL_STRIDE_;
        uint32_t u   = yr ? rec.y : rec.x;
        uint32_t pix = (u >> bsh) & 0xFFFFu;
        float2 wf = __half22float2(yr ? *(__half2*)&rec.w : *(__half2*)&rec.z);
        float  w  = xp ? wf.y : wf.x;
        uint2 v = *(const uint2*)(vl + (size_t)pix * HD_);
        a0 += w * __uint_as_float(v.x << 16);
        a1 += w * __uint_as_float(v.x & 0xFFFF0000u);
        a2 += w * __uint_as_float(v.y << 16);
        a3 += w * __uint_as_float(v.y & 0xFFFF0000u);
    }
    a0 += __shfl_xor_sync(0xffffffffu, a0, 8);
    a1 += __shfl_xor_sync(0xffffffffu, a1, 8);
    a2 += __shfl_xor_sync(0xffffffffu, a2, 8);
    a3 += __shfl_xor_sync(0xffffffffu, a3, 8);
    a0 += __shfl_xor_sync(0xffffffffu, a0, 16);
    a1 += __shfl_xor_sync(0xffffffffu, a1, 16);
    a2 += __shfl_xor_sync(0xffffffffu, a2, 16);
    a3 += __shfl_xor_sync(0xffffffffu, a3, 16);
    if (lane < 8) {
        __nv_bfloat162 o0, o1;
        o0.x = __float2bfloat16(a0);
        o0.y = __float2bfloat16(a1);
        o1.x = __float2bfloat16(a2);
        o1.y = __float2bfloat16(a3);
        uint2 st;
        st.x = *(uint32_t*)&o0;
        st.y = *(uint32_t*)&o1;
        *(uint2*)(g_samp + (size_t)r*C_ + h*HD_ + cq*4) = st;
    }
}

// ---------------------------------------------------------------------------
// Launch
// ---------------------------------------------------------------------------
extern "C" void kernel_launch(void* const* d_in, const int* in_sizes, int n_in,
                              void* d_out, int out_size)
{
    const float* x     = (const float*)d_in[0];
    const float* ref   = (const float*)d_in[1];
    const float* n3g   = (const float*)d_in[4];
    const float* n3b   = (const float*)d_in[5];
    const float* n4g   = (const float*)d_in[6];
    const float* n4b   = (const float*)d_in[7];
    const float* w_off = (const float*)d_in[8];
    const float* b_off = (const float*)d_in[9];
    const float* w_attn= (const float*)d_in[10];
    const float* b_attn= (const float*)d_in[11];
    const float* w_val = (const float*)d_in[12];
    const float* b_val = (const float*)d_in[13];
    const float* w_out = (const float*)d_in[14];
    const float* b_out = (const float*)d_in[15];
    const float* w_fc1 = (const float*)d_in[16];
    const float* b_fc1 = (const float*)d_in[17];
    const float* w_fc2 = (const float*)d_in[18];
    const float* b_fc2 = (const float*)d_in[19];
    float* out = (float*)d_out;

    __nv_bfloat16 *p_q, *p_samp, *p_h, *p_mlp;
    __nv_bfloat16 *p_wproj, *p_wout, *p_wfc1, *p_wfc2;
    cudaGetSymbolAddress((void**)&p_q,    g_q);
    cudaGetSymbolAddress((void**)&p_samp, g_samp);
    cudaGetSymbolAddress((void**)&p_h,    g_h);
    cudaGetSymbolAddress((void**)&p_mlp,  g_mlp);
    cudaGetSymbolAddress((void**)&p_wproj,g_wproj);
    cudaGetSymbolAddress((void**)&p_wout, g_wout);
    cudaGetSymbolAddress((void**)&p_wfc1, g_wfc1);
    cudaGetSymbolAddress((void**)&p_wfc2, g_wfc2);

    // fused weight transpose+convert (all weights, one launch)
    tcvt6_kernel<<<1120, dim3(32,32)>>>(
        w_val, w_off, w_attn, w_out, w_fc1, w_fc2,
        p_wproj, p_wout, p_wfc1, p_wfc2);

    // 1) LN3 -> q (bf16)
    ln_kernel<<<M_, 256>>>(x, n3g, n3b, p_q);

    // 2) fused projections: val (head-major bf16) + offsets + attn logits
    gemm_proj<<<dim3(NPROJ_/128, M_/128), 256>>>(p_q, b_val, b_off, b_attn);

    // 3) fused softmax + sample prep -> g_rec
    softmax_prep_kernel<<<M_, 256>>>(ref);

    // 4) gather -> g_samp (bf16)
    gather_kernel<<<M_, 256>>>();

    // 5) out projection + residual(x) -> d_out (fp32)
    gemm_hmma<0,1,0><<<dim3(C_/128, M_/128), 256>>>(
        M_, C_, C_, p_samp, p_wout, b_out, x, out, nullptr);

    // 6) LN4 -> h (bf16)
    ln_kernel<<<M_, 256>>>(out, n4g, n4b, p_h);

    // 7) fc1 + GELU -> bf16
    gemm_hmma<1,0,1><<<dim3(MLP_H_/128, M_/128), 256>>>(
        M_, MLP_H_, C_, p_h, p_wfc1, b_fc1, nullptr, nullptr, p_mlp);

    // 8) fc2 + residual(d_out) -> d_out (fp32, in-place elementwise-safe)
    gemm_hmma<0,1,0><<<dim3(C_/128, M_/128), 256>>>(
        M_, C_, MLP_H_, p_mlp, p_wfc2, b_fc2, out, out, nullptr);
}

// round 6
// speedup vs baseline: 4.1960x; 1.2075x over previous
#include <cuda_runtime.h>
#include <cuda_bf16.h>
#include <cuda_fp16.h>
#include <math.h>
#include <stdint.h>

// Problem constants
#define B_    2
#define D_    5
#define H_    32
#define W_    32
#define C_    256
#define NH_   8
#define NL_   5
#define NP_   16
#define HD_   32
#define HW_   (H_*W_)          // 1024
#define LQ_   (D_*HW_)         // 5120
#define M_    (B_*LQ_)         // 10240
#define MLP_H_ 1024
#define PTS_  (NL_*NP_)        // 80
#define NPROJ_ 2176            // 256 (val) + 1280 (off) + 640 (attn)
#define LVL_STRIDE_ (NH_*HW_*HD_)   // elements per level (head-major val)

// ---------------- scratch (device globals; no allocation) ----------------
__device__ __nv_bfloat16 g_q   [M_*C_];            // LN3 out (bf16)
__device__ __nv_bfloat16 g_valh[B_*NL_*NH_*HW_*HD_]; // value, head-major layout
__device__ float         g_off [M_*NH_*PTS_*2];    // offsets fp32
__device__ float         g_attn[M_*NH_*PTS_];      // attn logits fp32
__device__ __nv_bfloat16 g_samp[M_*C_];            // sampled attn (bf16)
__device__ __nv_bfloat16 g_h   [M_*C_];            // LN4 out (bf16)
__device__ __nv_bfloat16 g_mlp [M_*MLP_H_];        // fc1+GELU (bf16)
// transposed bf16 weights [N,K]
__device__ __nv_bfloat16 g_wproj[NPROJ_*C_];       // concat: val|off|attn rows
__device__ __nv_bfloat16 g_wout [C_*C_];
__device__ __nv_bfloat16 g_wfc1 [MLP_H_*C_];
__device__ __nv_bfloat16 g_wfc2 [C_*MLP_H_];

__device__ __forceinline__ uint32_t smem_u32(const void* p) {
    uint32_t a;
    asm("{ .reg .u64 t; cvta.to.shared.u64 t, %1; cvt.u32.u64 %0, t; }" : "=r"(a) : "l"(p));
    return a;
}
__device__ __forceinline__ void cp_async16(uint32_t s, const void* g) {
    asm volatile("cp.async.cg.shared.global [%0], [%1], 16;" :: "r"(s), "l"(g) : "memory");
}
__device__ __forceinline__ void cp_commit() {
    asm volatile("cp.async.commit_group;" ::: "memory");
}
__device__ __forceinline__ void cp_wait1() {
    asm volatile("cp.async.wait_group 1;" ::: "memory");
}
__device__ __forceinline__ void ldmx4(uint32_t& r0, uint32_t& r1, uint32_t& r2, uint32_t& r3, uint32_t a) {
    asm volatile("ldmatrix.sync.aligned.m8n8.x4.shared.b16 {%0,%1,%2,%3}, [%4];"
                 : "=r"(r0), "=r"(r1), "=r"(r2), "=r"(r3) : "r"(a));
}
__device__ __forceinline__ void ldmx2(uint32_t& r0, uint32_t& r1, uint32_t a) {
    asm volatile("ldmatrix.sync.aligned.m8n8.x2.shared.b16 {%0,%1}, [%2];"
                 : "=r"(r0), "=r"(r1) : "r"(a));
}
__device__ __forceinline__ void mma_bf16(float* c, const uint32_t* a, const uint32_t* b) {
    asm volatile(
        "mma.sync.aligned.m16n8k16.row.col.f32.bf16.bf16.f32 "
        "{%0,%1,%2,%3}, {%4,%5,%6,%7}, {%8,%9}, {%0,%1,%2,%3};"
        : "+f"(c[0]), "+f"(c[1]), "+f"(c[2]), "+f"(c[3])
        : "r"(a[0]), "r"(a[1]), "r"(a[2]), "r"(a[3]), "r"(b[0]), "r"(b[1]));
}

// ---------------------------------------------------------------------------
// LayerNorm: block(256) per row, writes bf16
// ---------------------------------------------------------------------------
__global__ void ln_kernel(const float* __restrict__ x,
                          const float* __restrict__ g,
                          const float* __restrict__ b,
                          __nv_bfloat16* __restrict__ out)
{
    int row = blockIdx.x;
    int c   = threadIdx.x;
    float v = x[(size_t)row*C_ + c];
    float sum = v, sq = v*v;
    #pragma unroll
    for (int o = 16; o > 0; o >>= 1) {
        sum += __shfl_xor_sync(0xffffffffu, sum, o);
        sq  += __shfl_xor_sync(0xffffffffu, sq , o);
    }
    __shared__ float s1[8], s2[8];
    int w = c >> 5, l = c & 31;
    if (l == 0) { s1[w] = sum; s2[w] = sq; }
    __syncthreads();
    sum = 0.f; sq = 0.f;
    #pragma unroll
    for (int i = 0; i < 8; i++) { sum += s1[i]; sq += s2[i]; }
    float m   = sum * (1.f / C_);
    float var = sq  * (1.f / C_) - m*m;
    float inv = rsqrtf(var + 1e-5f);
    out[(size_t)row*C_ + c] = __float2bfloat16((v - m) * inv * g[c] + b[c]);
}

// ---------------------------------------------------------------------------
// Fused weight transpose+convert: all weights, one launch.
// in [K,N] fp32 -> out [N,K] bf16; one 32x32 tile per block. (1120 tiles)
// ---------------------------------------------------------------------------
__global__ void tcvt6_kernel(
    const float* __restrict__ s0, const float* __restrict__ s1,
    const float* __restrict__ s2, const float* __restrict__ s3,
    const float* __restrict__ s4, const float* __restrict__ s5,
    __nv_bfloat16* __restrict__ dproj,
    __nv_bfloat16* __restrict__ d3,
    __nv_bfloat16* __restrict__ d4, __nv_bfloat16* __restrict__ d5)
{
    int t = blockIdx.x;
    const float* src; __nv_bfloat16* dst; int K, N;
    if      (t < 64)  { src=s0; dst=dproj;              K=256;  N=256;          }
    else if (t < 384) { src=s1; dst=dproj + 256*256;    K=256;  N=1280; t-=64;  }
    else if (t < 544) { src=s2; dst=dproj + 1536*256;   K=256;  N=640;  t-=384; }
    else if (t < 608) { src=s3; dst=d3;                 K=256;  N=256;  t-=544; }
    else if (t < 864) { src=s4; dst=d4;                 K=256;  N=1024; t-=608; }
    else              { src=s5; dst=d5;                 K=1024; N=256;  t-=864; }
    int bx = t % (N/32), by = t / (N/32);

    __shared__ float tl[32][33];
    int k = by*32 + threadIdx.y;
    int n = bx*32 + threadIdx.x;
    tl[threadIdx.y][threadIdx.x] = src[(size_t)k*N + n];
    __syncthreads();
    int on = bx*32 + threadIdx.y;
    int ok = by*32 + threadIdx.x;
    dst[(size_t)on*K + ok] = __float2bfloat16(tl[threadIdx.x][threadIdx.y]);
}

// ---------------------------------------------------------------------------
// GEMM config: 128x128 tile, BK=32, 256 thr, 8 warps.
// ---------------------------------------------------------------------------
#define BK_ 32
#define LDS_ 40   // padded row stride (elements)

// Generic HMMA GEMM (out/fc1/fc2): + bias, optional GELU, optional residual.
template<int ACT, int RES, int BF16OUT>
__global__ void __launch_bounds__(256) gemm_hmma(
    int M, int N, int K,
    const __nv_bfloat16* __restrict__ A,
    const __nv_bfloat16* __restrict__ Bw,
    const float* __restrict__ bias,
    const float* __restrict__ res,
    float* __restrict__ Cf,
    __nv_bfloat16* __restrict__ Cb)
{
    __shared__ __nv_bfloat16 As[2][128][LDS_];
    __shared__ __nv_bfloat16 Bs[2][128][LDS_];

    int tid  = threadIdx.x;
    int lane = tid & 31;
    int wid  = tid >> 5;
    int wm   = wid & 3;
    int wn   = wid >> 2;

    int brow = blockIdx.y * 128;
    int bcol = blockIdx.x * 128;
    const int NIT = K / BK_;

    int r0c = tid >> 2;
    int c0c = (tid & 3) * 8;

    auto load_tile = [&](int it, int buf) {
        const __nv_bfloat16* ag = A  + (size_t)(brow + r0c) * K + it*BK_ + c0c;
        cp_async16(smem_u32(&As[buf][r0c][c0c]),      ag);
        cp_async16(smem_u32(&As[buf][r0c+64][c0c]),   ag + (size_t)64*K);
        const __nv_bfloat16* bg = Bw + (size_t)(bcol + r0c) * K + it*BK_ + c0c;
        cp_async16(smem_u32(&Bs[buf][r0c][c0c]),      bg);
        cp_async16(smem_u32(&Bs[buf][r0c+64][c0c]),   bg + (size_t)64*K);
    };

    float acc[2][8][4];
    #pragma unroll
    for (int mi = 0; mi < 2; mi++)
        #pragma unroll
        for (int ni = 0; ni < 8; ni++)
            #pragma unroll
            for (int k = 0; k < 4; k++) acc[mi][ni][k] = 0.f;

    load_tile(0, 0); cp_commit();
    load_tile(1, 1); cp_commit();

    for (int it = 0; it < NIT; ++it) {
        cp_wait1();
        __syncthreads();
        int cur = it & 1;

        #pragma unroll
        for (int kk = 0; kk < 2; kk++) {
            int k0 = kk * 16;
            uint32_t af[2][4], bfr[8][2];
            #pragma unroll
            for (int mi = 0; mi < 2; mi++) {
                uint32_t addr = smem_u32(&As[cur][wm*32 + mi*16 + (lane & 15)]
                                                [k0 + (lane >> 4) * 8]);
                ldmx4(af[mi][0], af[mi][1], af[mi][2], af[mi][3], addr);
            }
            #pragma unroll
            for (int ni = 0; ni < 8; ni++) {
                uint32_t addr = smem_u32(&Bs[cur][wn*64 + ni*8 + (lane & 7)]
                                                [k0 + ((lane >> 3) & 1) * 8]);
                ldmx2(bfr[ni][0], bfr[ni][1], addr);
            }
            #pragma unroll
            for (int mi = 0; mi < 2; mi++)
                #pragma unroll
                for (int ni = 0; ni < 8; ni++)
                    mma_bf16(acc[mi][ni], af[mi], bfr[ni]);
        }
        __syncthreads();
        if (it + 2 < NIT) load_tile(it + 2, cur);
        cp_commit();
    }

    int gq = lane >> 2, tq = lane & 3;
    #pragma unroll
    for (int mi = 0; mi < 2; mi++) {
        #pragma unroll
        for (int half = 0; half < 2; half++) {
            int row = brow + wm*32 + mi*16 + half*8 + gq;
            #pragma unroll
            for (int ni = 0; ni < 8; ni++) {
                int col = bcol + wn*64 + ni*8 + tq*2;
                float v0 = acc[mi][ni][half*2 + 0] + bias[col];
                float v1 = acc[mi][ni][half*2 + 1] + bias[col + 1];
                if (ACT == 1) {
                    v0 = 0.5f * v0 * (1.f + erff(v0 * 0.70710678118654752f));
                    v1 = 0.5f * v1 * (1.f + erff(v1 * 0.70710678118654752f));
                }
                if (RES) {
                    const float2 r2 = *(const float2*)&res[(size_t)row * N + col];
                    v0 += r2.x; v1 += r2.y;
                }
                if (BF16OUT) {
                    __nv_bfloat162 o;
                    o.x = __float2bfloat16(v0);
                    o.y = __float2bfloat16(v1);
                    *(__nv_bfloat162*)&Cb[(size_t)row * N + col] = o;
                } else {
                    float2 o; o.x = v0; o.y = v1;
                    *(float2*)&Cf[(size_t)row * N + col] = o;
                }
            }
        }
    }
}

// ---------------------------------------------------------------------------
// Fused projection GEMM: A[M,256] @ Wproj[2176,256]^T. Epilogue routes by
// column region: val -> bf16 head-major g_valh, off/attn -> fp32.
// ---------------------------------------------------------------------------
__global__ void __launch_bounds__(256) gemm_proj(
    const __nv_bfloat16* __restrict__ A,
    const float* __restrict__ bv,
    const float* __restrict__ bo,
    const float* __restrict__ ba)
{
    const int K = C_;
    __shared__ __nv_bfloat16 As[2][128][LDS_];
    __shared__ __nv_bfloat16 Bs[2][128][LDS_];

    int tid  = threadIdx.x;
    int lane = tid & 31;
    int wid  = tid >> 5;
    int wm   = wid & 3;
    int wn   = wid >> 2;

    int brow = blockIdx.y * 128;
    int bcol = blockIdx.x * 128;
    const int NIT = K / BK_;

    int r0c = tid >> 2;
    int c0c = (tid & 3) * 8;
    const __nv_bfloat16* Bw = g_wproj;

    auto load_tile = [&](int it, int buf) {
        const __nv_bfloat16* ag = A  + (size_t)(brow + r0c) * K + it*BK_ + c0c;
        cp_async16(smem_u32(&As[buf][r0c][c0c]),      ag);
        cp_async16(smem_u32(&As[buf][r0c+64][c0c]),   ag + (size_t)64*K);
        const __nv_bfloat16* bg = Bw + (size_t)(bcol + r0c) * K + it*BK_ + c0c;
        cp_async16(smem_u32(&Bs[buf][r0c][c0c]),      bg);
        cp_async16(smem_u32(&Bs[buf][r0c+64][c0c]),   bg + (size_t)64*K);
    };

    float acc[2][8][4];
    #pragma unroll
    for (int mi = 0; mi < 2; mi++)
        #pragma unroll
        for (int ni = 0; ni < 8; ni++)
            #pragma unroll
            for (int k = 0; k < 4; k++) acc[mi][ni][k] = 0.f;

    load_tile(0, 0); cp_commit();
    load_tile(1, 1); cp_commit();

    for (int it = 0; it < NIT; ++it) {
        cp_wait1();
        __syncthreads();
        int cur = it & 1;
        #pragma unroll
        for (int kk = 0; kk < 2; kk++) {
            int k0 = kk * 16;
            uint32_t af[2][4], bfr[8][2];
            #pragma unroll
            for (int mi = 0; mi < 2; mi++) {
                uint32_t addr = smem_u32(&As[cur][wm*32 + mi*16 + (lane & 15)]
                                                [k0 + (lane >> 4) * 8]);
                ldmx4(af[mi][0], af[mi][1], af[mi][2], af[mi][3], addr);
            }
            #pragma unroll
            for (int ni = 0; ni < 8; ni++) {
                uint32_t addr = smem_u32(&Bs[cur][wn*64 + ni*8 + (lane & 7)]
                                                [k0 + ((lane >> 3) & 1) * 8]);
                ldmx2(bfr[ni][0], bfr[ni][1], addr);
            }
            #pragma unroll
            for (int mi = 0; mi < 2; mi++)
                #pragma unroll
                for (int ni = 0; ni < 8; ni++)
                    mma_bf16(acc[mi][ni], af[mi], bfr[ni]);
        }
        __syncthreads();
        if (it + 2 < NIT) load_tile(it + 2, cur);
        cp_commit();
    }

    int gq = lane >> 2, tq = lane & 3;
    if (bcol < 256) {
        #pragma unroll
        for (int mi = 0; mi < 2; mi++)
            #pragma unroll
            for (int half = 0; half < 2; half++) {
                int row = brow + wm*32 + mi*16 + half*8 + gq;
                int bb  = row / LQ_;
                int rem = row - bb*LQ_;
                int d   = rem >> 10;
                int pix = rem & 1023;
                size_t tokbase = ((size_t)((bb*NL_ + d)*NH_) * HW_ + pix) * HD_;
                #pragma unroll
                for (int ni = 0; ni < 8; ni++) {
                    int col = bcol + wn*64 + ni*8 + tq*2;
                    int h  = col >> 5;
                    int hd = col & 31;
                    float v0 = acc[mi][ni][half*2 + 0] + bv[col];
                    float v1 = acc[mi][ni][half*2 + 1] + bv[col + 1];
                    __nv_bfloat162 o;
                    o.x = __float2bfloat16(v0);
                    o.y = __float2bfloat16(v1);
                    *(__nv_bfloat162*)&g_valh[tokbase + (size_t)h*HW_*HD_ + hd] = o;
                }
            }
    } else if (bcol < 1536) {
        #pragma unroll
        for (int mi = 0; mi < 2; mi++)
            #pragma unroll
            for (int half = 0; half < 2; half++) {
                int row = brow + wm*32 + mi*16 + half*8 + gq;
                #pragma unroll
                for (int ni = 0; ni < 8; ni++) {
                    int col = bcol - 256 + wn*64 + ni*8 + tq*2;
                    float2 o;
                    o.x = acc[mi][ni][half*2 + 0] + bo[col];
                    o.y = acc[mi][ni][half*2 + 1] + bo[col + 1];
                    *(float2*)&g_off[(size_t)row * 1280 + col] = o;
                }
            }
    } else {
        #pragma unroll
        for (int mi = 0; mi < 2; mi++)
            #pragma unroll
            for (int half = 0; half < 2; half++) {
                int row = brow + wm*32 + mi*16 + half*8 + gq;
                #pragma unroll
                for (int ni = 0; ni < 8; ni++) {
                    int col = bcol - 1536 + wn*64 + ni*8 + tq*2;
                    float2 o;
                    o.x = acc[mi][ni][half*2 + 0] + ba[col];
                    o.y = acc[mi][ni][half*2 + 1] + ba[col + 1];
                    *(float2*)&g_attn[(size_t)row * 640 + col] = o;
                }
            }
    }
}

// ---------------------------------------------------------------------------
// FUSED softmax + prep + gather. Block = token, warp = head.
// Phase 1 (per warp): softmax over 80 logits; lane j computes records for
//   points {j, j+32, j+64}: packed u16 clamped pixel pairs + fp16 weights
//   (attn prob & validity folded) -> smem (warp-private region, __syncwarp).
// Phase 2: 2 points/iter. lane = (pt-half, yrow, xhalf, chanquad):
//   each lane LDG.128 = 8 chans of its corner; fp32 accum (8 regs);
//   reduce via shfl_xor 16/8/4; lanes 0-3 store uint4 -> g_samp.
// ---------------------------------------------------------------------------
__global__ void __launch_bounds__(256) sample_fused_kernel(const float* __restrict__ ref)
{
    __shared__ uint4 s_rec[NH_][PTS_];

    int r    = blockIdx.x;
    int h    = threadIdx.x >> 5;
    int lane = threadIdx.x & 31;
    int b    = r / LQ_;

    // ---- Phase 1: softmax + record build ----
    {
        const float* p = g_attn + (size_t)r * (NH_*PTS_) + h * PTS_;
        float v0 = p[lane];
        float v1 = p[lane + 32];
        float v2 = (lane < 16) ? p[lane + 64] : -1e30f;
        float mx = fmaxf(v0, fmaxf(v1, v2));
        #pragma unroll
        for (int o = 16; o > 0; o >>= 1) mx = fmaxf(mx, __shfl_xor_sync(0xffffffffu, mx, o));
        float e0 = expf(v0 - mx);
        float e1 = expf(v1 - mx);
        float e2 = (lane < 16) ? expf(v2 - mx) : 0.f;
        float s = e0 + e1 + e2;
        #pragma unroll
        for (int o = 16; o > 0; o >>= 1) s += __shfl_xor_sync(0xffffffffu, s, o);
        float inv = 1.f / s;
        float prob[3] = { e0 * inv, e1 * inv, e2 * inv };

        const float2* offp = (const float2*)(g_off + (size_t)r * (NH_*PTS_*2) + h * (PTS_*2));
        const float* refr = ref + (size_t)r * (NL_*2);

        #pragma unroll
        for (int j = 0; j < 3; j++) {
            int it = lane + j*32;
            if (it < PTS_) {
                int l = it >> 4;
                float2 o2 = offp[it];
                float px = refr[l*2 + 0] * (float)W_ + o2.x - 0.5f;
                float py = refr[l*2 + 1] * (float)H_ + o2.y - 0.5f;
                float x0f = floorf(px), y0f = floorf(py);
                float fx = px - x0f, fy = py - y0f;
                int x0 = (int)x0f, y0 = (int)y0f;
                float aw = prob[j];
                float w00 = aw*(1.f-fy)*(1.f-fx);
                float w01 = aw*(1.f-fy)*fx;
                float w10 = aw*fy*(1.f-fx);
                float w11 = aw*fy*fx;
                if (!(((unsigned)y0     < (unsigned)H_) && ((unsigned)x0     < (unsigned)W_))) w00 = 0.f;
                if (!(((unsigned)y0     < (unsigned)H_) && ((unsigned)(x0+1) < (unsigned)W_))) w01 = 0.f;
                if (!(((unsigned)(y0+1) < (unsigned)H_) && ((unsigned)x0     < (unsigned)W_))) w10 = 0.f;
                if (!(((unsigned)(y0+1) < (unsigned)H_) && ((unsigned)(x0+1) < (unsigned)W_))) w11 = 0.f;
                int xc0 = min(max(x0,     0), W_-1);
                int xc1 = min(max(x0 + 1, 0), W_-1);
                int yc0 = min(max(y0,     0), H_-1);
                int yc1 = min(max(y0 + 1, 0), H_-1);
                uint4 rec;
                rec.x = (uint32_t)(yc0*W_ + xc0) | ((uint32_t)(yc0*W_ + xc1) << 16);
                rec.y = (uint32_t)(yc1*W_ + xc0) | ((uint32_t)(yc1*W_ + xc1) << 16);
                __half2 h01 = __floats2half2_rn(w00, w01);
                __half2 h23 = __floats2half2_rn(w10, w11);
                rec.z = *(uint32_t*)&h01;
                rec.w = *(uint32_t*)&h23;
                s_rec[h][it] = rec;
            }
        }
    }
    __syncwarp();

    // ---- Phase 2: gather, 2 points per iteration ----
    int hw   = lane >> 4;        // which of the 2 points this iter
    int yr   = (lane >> 3) & 1;  // corner row
    int xh   = (lane >> 2) & 1;  // corner column
    int cg   = lane & 3;         // channel group (8 chans = 16B)
    int bsh  = xh * 16;

    const __nv_bfloat16* vb0 = g_valh
        + (size_t)((b*NL_)*NH_ + h) * (HW_*HD_) + cg*8;

    float a0=0.f, a1=0.f, a2=0.f, a3=0.f, a4=0.f, a5=0.f, a6=0.f, a7=0.f;
    #pragma unroll 4
    for (int i = 0; i < PTS_/2; i++) {
        uint4 rec = s_rec[h][2*i + hw];
        int l = (2*i + hw) >> 4;
        uint32_t u   = yr ? rec.y : rec.x;
        uint32_t pix = (u >> bsh) & 0xFFFFu;
        float2 wf = __half22float2(yr ? *(__half2*)&rec.w : *(__half2*)&rec.z);
        float  w  = xh ? wf.y : wf.x;
        uint4 v = *(const uint4*)(vb0 + (size_t)l * LVL_STRIDE_ + (size_t)pix * HD_);
        a0 += w * __uint_as_float(v.x << 16);
        a1 += w * __uint_as_float(v.x & 0xFFFF0000u);
        a2 += w * __uint_as_float(v.y << 16);
        a3 += w * __uint_as_float(v.y & 0xFFFF0000u);
        a4 += w * __uint_as_float(v.z << 16);
        a5 += w * __uint_as_float(v.z & 0xFFFF0000u);
        a6 += w * __uint_as_float(v.w << 16);
        a7 += w * __uint_as_float(v.w & 0xFFFF0000u);
    }
    #pragma unroll
    for (int o = 16; o >= 4; o >>= 1) {
        a0 += __shfl_xor_sync(0xffffffffu, a0, o);
        a1 += __shfl_xor_sync(0xffffffffu, a1, o);
        a2 += __shfl_xor_sync(0xffffffffu, a2, o);
        a3 += __shfl_xor_sync(0xffffffffu, a3, o);
        a4 += __shfl_xor_sync(0xffffffffu, a4, o);
        a5 += __shfl_xor_sync(0xffffffffu, a5, o);
        a6 += __shfl_xor_sync(0xffffffffu, a6, o);
        a7 += __shfl_xor_sync(0xffffffffu, a7, o);
    }
    if (lane < 4) {
        __nv_bfloat162 o0, o1, o2, o3;
        o0.x = __float2bfloat16(a0); o0.y = __float2bfloat16(a1);
        o1.x = __float2bfloat16(a2); o1.y = __float2bfloat16(a3);
        o2.x = __float2bfloat16(a4); o2.y = __float2bfloat16(a5);
        o3.x = __float2bfloat16(a6); o3.y = __float2bfloat16(a7);
        uint4 st;
        st.x = *(uint32_t*)&o0; st.y = *(uint32_t*)&o1;
        st.z = *(uint32_t*)&o2; st.w = *(uint32_t*)&o3;
        *(uint4*)(g_samp + (size_t)r*C_ + h*HD_ + cg*8) = st;
    }
}

// ---------------------------------------------------------------------------
// Launch
// ---------------------------------------------------------------------------
extern "C" void kernel_launch(void* const* d_in, const int* in_sizes, int n_in,
                              void* d_out, int out_size)
{
    const float* x     = (const float*)d_in[0];
    const float* ref   = (const float*)d_in[1];
    const float* n3g   = (const float*)d_in[4];
    const float* n3b   = (const float*)d_in[5];
    const float* n4g   = (const float*)d_in[6];
    const float* n4b   = (const float*)d_in[7];
    const float* w_off = (const float*)d_in[8];
    const float* b_off = (const float*)d_in[9];
    const float* w_attn= (const float*)d_in[10];
    const float* b_attn= (const float*)d_in[11];
    const float* w_val = (const float*)d_in[12];
    const float* b_val = (const float*)d_in[13];
    const float* w_out = (const float*)d_in[14];
    const float* b_out = (const float*)d_in[15];
    const float* w_fc1 = (const float*)d_in[16];
    const float* b_fc1 = (const float*)d_in[17];
    const float* w_fc2 = (const float*)d_in[18];
    const float* b_fc2 = (const float*)d_in[19];
    float* out = (float*)d_out;

    __nv_bfloat16 *p_q, *p_samp, *p_h, *p_mlp;
    __nv_bfloat16 *p_wproj, *p_wout, *p_wfc1, *p_wfc2;
    cudaGetSymbolAddress((void**)&p_q,    g_q);
    cudaGetSymbolAddress((void**)&p_samp, g_samp);
    cudaGetSymbolAddress((void**)&p_h,    g_h);
    cudaGetSymbolAddress((void**)&p_mlp,  g_mlp);
    cudaGetSymbolAddress((void**)&p_wproj,g_wproj);
    cudaGetSymbolAddress((void**)&p_wout, g_wout);
    cudaGetSymbolAddress((void**)&p_wfc1, g_wfc1);
    cudaGetSymbolAddress((void**)&p_wfc2, g_wfc2);

    // fused weight transpose+convert (all weights, one launch)
    tcvt6_kernel<<<1120, dim3(32,32)>>>(
        w_val, w_off, w_attn, w_out, w_fc1, w_fc2,
        p_wproj, p_wout, p_wfc1, p_wfc2);

    // 1) LN3 -> q (bf16)
    ln_kernel<<<M_, 256>>>(x, n3g, n3b, p_q);

    // 2) fused projections: val (head-major bf16) + offsets + attn logits
    gemm_proj<<<dim3(NPROJ_/128, M_/128), 256>>>(p_q, b_val, b_off, b_attn);

    // 3) fused softmax + prep + gather -> g_samp (bf16)
    sample_fused_kernel<<<M_, 256>>>(ref);

    // 4) out projection + residual(x) -> d_out (fp32)
    gemm_hmma<0,1,0><<<dim3(C_/128, M_/128), 256>>>(
        M_, C_, C_, p_samp, p_wout, b_out, x, out, nullptr);

    // 5) LN4 -> h (bf16)
    ln_kernel<<<M_, 256>>>(out, n4g, n4b, p_h);

    // 6) fc1 + GELU -> bf16
    gemm_hmma<1,0,1><<<dim3(MLP_H_/128, M_/128), 256>>>(
        M_, MLP_H_, C_, p_h, p_wfc1, b_fc1, nullptr, nullptr, p_mlp);

    // 7) fc2 + residual(d_out) -> d_out (fp32, in-place elementwise-safe)
    gemm_hmma<0,1,0><<<dim3(C_/128, M_/128), 256>>>(
        M_, C_, MLP_H_, p_mlp, p_wfc2, b_fc2, out, out, nullptr);
}

// round 7
// speedup vs baseline: 4.9458x; 1.1787x over previous
#include <cuda_runtime.h>
#include <cuda_bf16.h>
#include <cuda_fp16.h>
#include <math.h>
#include <stdint.h>

// Problem constants
#define B_    2
#define D_    5
#define H_    32
#define W_    32
#define C_    256
#define NH_   8
#define NL_   5
#define NP_   16
#define HD_   32
#define HW_   (H_*W_)          // 1024
#define LQ_   (D_*HW_)         // 5120
#define M_    (B_*LQ_)         // 10240
#define MLP_H_ 1024
#define PTS_  (NL_*NP_)        // 80
#define NPROJ_ 2176            // 256 (val) + 1280 (off) + 640 (attn)
#define LVL_STRIDE_ (NH_*HW_*HD_)   // elements per level (head-major val)

// ---------------- scratch (device globals; no allocation) ----------------
__device__ __nv_bfloat16 g_q   [M_*C_];
__device__ __nv_bfloat16 g_valh[B_*NL_*NH_*HW_*HD_]; // value, head-major
__device__ float         g_off [M_*NH_*PTS_*2];
__device__ float         g_attn[M_*NH_*PTS_];
__device__ __nv_bfloat16 g_samp[M_*C_];
__device__ __nv_bfloat16 g_h   [M_*C_];
__device__ __nv_bfloat16 g_mlp [M_*MLP_H_];
// transposed bf16 weights [N,K]
__device__ __nv_bfloat16 g_wproj[NPROJ_*C_];
__device__ __nv_bfloat16 g_wout [C_*C_];
__device__ __nv_bfloat16 g_wfc1 [MLP_H_*C_];
__device__ __nv_bfloat16 g_wfc2 [C_*MLP_H_];

__device__ __forceinline__ uint32_t smem_u32(const void* p) {
    uint32_t a;
    asm("{ .reg .u64 t; cvta.to.shared.u64 t, %1; cvt.u32.u64 %0, t; }" : "=r"(a) : "l"(p));
    return a;
}
__device__ __forceinline__ void cp_async16(uint32_t s, const void* g) {
    asm volatile("cp.async.cg.shared.global [%0], [%1], 16;" :: "r"(s), "l"(g) : "memory");
}
__device__ __forceinline__ void cp_commit() {
    asm volatile("cp.async.commit_group;" ::: "memory");
}
__device__ __forceinline__ void cp_wait1() {
    asm volatile("cp.async.wait_group 1;" ::: "memory");
}
__device__ __forceinline__ void ldmx4(uint32_t& r0, uint32_t& r1, uint32_t& r2, uint32_t& r3, uint32_t a) {
    asm volatile("ldmatrix.sync.aligned.m8n8.x4.shared.b16 {%0,%1,%2,%3}, [%4];"
                 : "=r"(r0), "=r"(r1), "=r"(r2), "=r"(r3) : "r"(a));
}
__device__ __forceinline__ void ldmx2(uint32_t& r0, uint32_t& r1, uint32_t a) {
    asm volatile("ldmatrix.sync.aligned.m8n8.x2.shared.b16 {%0,%1}, [%2];"
                 : "=r"(r0), "=r"(r1) : "r"(a));
}
__device__ __forceinline__ void mma_bf16(float* c, const uint32_t* a, const uint32_t* b) {
    asm volatile(
        "mma.sync.aligned.m16n8k16.row.col.f32.bf16.bf16.f32 "
        "{%0,%1,%2,%3}, {%4,%5,%6,%7}, {%8,%9}, {%0,%1,%2,%3};"
        : "+f"(c[0]), "+f"(c[1]), "+f"(c[2]), "+f"(c[3])
        : "r"(a[0]), "r"(a[1]), "r"(a[2]), "r"(a[3]), "r"(b[0]), "r"(b[1]));
}
// packed f32x2 helpers (sm_100-family PTX)
__device__ __forceinline__ uint64_t pack2(uint32_t lo, uint32_t hi) {
    uint64_t r; asm("mov.b64 %0, {%1, %2};" : "=l"(r) : "r"(lo), "r"(hi)); return r;
}
__device__ __forceinline__ void unpack2(uint64_t v, float& lo, float& hi) {
    uint32_t a, b; asm("mov.b64 {%0, %1}, %2;" : "=r"(a), "=r"(b) : "l"(v));
    lo = __uint_as_float(a); hi = __uint_as_float(b);
}
__device__ __forceinline__ void fma2(uint64_t& acc, uint64_t v, uint64_t w) {
    asm("fma.rn.f32x2 %0, %1, %2, %0;" : "+l"(acc) : "l"(v), "l"(w));
}

// ---------------------------------------------------------------------------
// LayerNorm: block(256) per row, writes bf16
// ---------------------------------------------------------------------------
__global__ void ln_kernel(const float* __restrict__ x,
                          const float* __restrict__ g,
                          const float* __restrict__ b,
                          __nv_bfloat16* __restrict__ out)
{
    int row = blockIdx.x;
    int c   = threadIdx.x;
    float v = x[(size_t)row*C_ + c];
    float sum = v, sq = v*v;
    #pragma unroll
    for (int o = 16; o > 0; o >>= 1) {
        sum += __shfl_xor_sync(0xffffffffu, sum, o);
        sq  += __shfl_xor_sync(0xffffffffu, sq , o);
    }
    __shared__ float s1[8], s2[8];
    int w = c >> 5, l = c & 31;
    if (l == 0) { s1[w] = sum; s2[w] = sq; }
    __syncthreads();
    sum = 0.f; sq = 0.f;
    #pragma unroll
    for (int i = 0; i < 8; i++) { sum += s1[i]; sq += s2[i]; }
    float m   = sum * (1.f / C_);
    float var = sq  * (1.f / C_) - m*m;
    float inv = rsqrtf(var + 1e-5f);
    out[(size_t)row*C_ + c] = __float2bfloat16((v - m) * inv * g[c] + b[c]);
}

// ---------------------------------------------------------------------------
// Fused weight transpose+convert (1120 tiles of 32x32)
// ---------------------------------------------------------------------------
__global__ void tcvt6_kernel(
    const float* __restrict__ s0, const float* __restrict__ s1,
    const float* __restrict__ s2, const float* __restrict__ s3,
    const float* __restrict__ s4, const float* __restrict__ s5,
    __nv_bfloat16* __restrict__ dproj,
    __nv_bfloat16* __restrict__ d3,
    __nv_bfloat16* __restrict__ d4, __nv_bfloat16* __restrict__ d5)
{
    int t = blockIdx.x;
    const float* src; __nv_bfloat16* dst; int K, N;
    if      (t < 64)  { src=s0; dst=dproj;              K=256;  N=256;          }
    else if (t < 384) { src=s1; dst=dproj + 256*256;    K=256;  N=1280; t-=64;  }
    else if (t < 544) { src=s2; dst=dproj + 1536*256;   K=256;  N=640;  t-=384; }
    else if (t < 608) { src=s3; dst=d3;                 K=256;  N=256;  t-=544; }
    else if (t < 864) { src=s4; dst=d4;                 K=256;  N=1024; t-=608; }
    else              { src=s5; dst=d5;                 K=1024; N=256;  t-=864; }
    int bx = t % (N/32), by = t / (N/32);

    __shared__ float tl[32][33];
    int k = by*32 + threadIdx.y;
    int n = bx*32 + threadIdx.x;
    tl[threadIdx.y][threadIdx.x] = src[(size_t)k*N + n];
    __syncthreads();
    int on = bx*32 + threadIdx.y;
    int ok = by*32 + threadIdx.x;
    dst[(size_t)on*K + ok] = __float2bfloat16(tl[threadIdx.x][threadIdx.y]);
}

// ---------------------------------------------------------------------------
// GEMM config: 128x128 tile, BK=32, 256 thr, 8 warps.
// ---------------------------------------------------------------------------
#define BK_ 32
#define LDS_ 40

template<int ACT, int RES, int BF16OUT>
__global__ void __launch_bounds__(256) gemm_hmma(
    int M, int N, int K,
    const __nv_bfloat16* __restrict__ A,
    const __nv_bfloat16* __restrict__ Bw,
    const float* __restrict__ bias,
    const float* __restrict__ res,
    float* __restrict__ Cf,
    __nv_bfloat16* __restrict__ Cb)
{
    __shared__ __nv_bfloat16 As[2][128][LDS_];
    __shared__ __nv_bfloat16 Bs[2][128][LDS_];

    int tid  = threadIdx.x;
    int lane = tid & 31;
    int wid  = tid >> 5;
    int wm   = wid & 3;
    int wn   = wid >> 2;

    int brow = blockIdx.y * 128;
    int bcol = blockIdx.x * 128;
    const int NIT = K / BK_;

    int r0c = tid >> 2;
    int c0c = (tid & 3) * 8;

    auto load_tile = [&](int it, int buf) {
        const __nv_bfloat16* ag = A  + (size_t)(brow + r0c) * K + it*BK_ + c0c;
        cp_async16(smem_u32(&As[buf][r0c][c0c]),      ag);
        cp_async16(smem_u32(&As[buf][r0c+64][c0c]),   ag + (size_t)64*K);
        const __nv_bfloat16* bg = Bw + (size_t)(bcol + r0c) * K + it*BK_ + c0c;
        cp_async16(smem_u32(&Bs[buf][r0c][c0c]),      bg);
        cp_async16(smem_u32(&Bs[buf][r0c+64][c0c]),   bg + (size_t)64*K);
    };

    float acc[2][8][4];
    #pragma unroll
    for (int mi = 0; mi < 2; mi++)
        #pragma unroll
        for (int ni = 0; ni < 8; ni++)
            #pragma unroll
            for (int k = 0; k < 4; k++) acc[mi][ni][k] = 0.f;

    load_tile(0, 0); cp_commit();
    load_tile(1, 1); cp_commit();

    for (int it = 0; it < NIT; ++it) {
        cp_wait1();
        __syncthreads();
        int cur = it & 1;

        #pragma unroll
        for (int kk = 0; kk < 2; kk++) {
            int k0 = kk * 16;
            uint32_t af[2][4], bfr[8][2];
            #pragma unroll
            for (int mi = 0; mi < 2; mi++) {
                uint32_t addr = smem_u32(&As[cur][wm*32 + mi*16 + (lane & 15)]
                                                [k0 + (lane >> 4) * 8]);
                ldmx4(af[mi][0], af[mi][1], af[mi][2], af[mi][3], addr);
            }
            #pragma unroll
            for (int ni = 0; ni < 8; ni++) {
                uint32_t addr = smem_u32(&Bs[cur][wn*64 + ni*8 + (lane & 7)]
                                                [k0 + ((lane >> 3) & 1) * 8]);
                ldmx2(bfr[ni][0], bfr[ni][1], addr);
            }
            #pragma unroll
            for (int mi = 0; mi < 2; mi++)
                #pragma unroll
                for (int ni = 0; ni < 8; ni++)
                    mma_bf16(acc[mi][ni], af[mi], bfr[ni]);
        }
        __syncthreads();
        if (it + 2 < NIT) load_tile(it + 2, cur);
        cp_commit();
    }

    int gq = lane >> 2, tq = lane & 3;
    #pragma unroll
    for (int mi = 0; mi < 2; mi++) {
        #pragma unroll
        for (int half = 0; half < 2; half++) {
            int row = brow + wm*32 + mi*16 + half*8 + gq;
            #pragma unroll
            for (int ni = 0; ni < 8; ni++) {
                int col = bcol + wn*64 + ni*8 + tq*2;
                float v0 = acc[mi][ni][half*2 + 0] + bias[col];
                float v1 = acc[mi][ni][half*2 + 1] + bias[col + 1];
                if (ACT == 1) {
                    v0 = 0.5f * v0 * (1.f + erff(v0 * 0.70710678118654752f));
                    v1 = 0.5f * v1 * (1.f + erff(v1 * 0.70710678118654752f));
                }
                if (RES) {
                    const float2 r2 = *(const float2*)&res[(size_t)row * N + col];
                    v0 += r2.x; v1 += r2.y;
                }
                if (BF16OUT) {
                    __nv_bfloat162 o;
                    o.x = __float2bfloat16(v0);
                    o.y = __float2bfloat16(v1);
                    *(__nv_bfloat162*)&Cb[(size_t)row * N + col] = o;
                } else {
                    float2 o; o.x = v0; o.y = v1;
                    *(float2*)&Cf[(size_t)row * N + col] = o;
                }
            }
        }
    }
}

// ---------------------------------------------------------------------------
// Fused projection GEMM: A[M,256] @ Wproj[2176,256]^T, routed epilogue.
// ---------------------------------------------------------------------------
__global__ void __launch_bounds__(256) gemm_proj(
    const __nv_bfloat16* __restrict__ A,
    const float* __restrict__ bv,
    const float* __restrict__ bo,
    const float* __restrict__ ba)
{
    const int K = C_;
    __shared__ __nv_bfloat16 As[2][128][LDS_];
    __shared__ __nv_bfloat16 Bs[2][128][LDS_];

    int tid  = threadIdx.x;
    int lane = tid & 31;
    int wid  = tid >> 5;
    int wm   = wid & 3;
    int wn   = wid >> 2;

    int brow = blockIdx.y * 128;
    int bcol = blockIdx.x * 128;
    const int NIT = K / BK_;

    int r0c = tid >> 2;
    int c0c = (tid & 3) * 8;
    const __nv_bfloat16* Bw = g_wproj;

    auto load_tile = [&](int it, int buf) {
        const __nv_bfloat16* ag = A  + (size_t)(brow + r0c) * K + it*BK_ + c0c;
        cp_async16(smem_u32(&As[buf][r0c][c0c]),      ag);
        cp_async16(smem_u32(&As[buf][r0c+64][c0c]),   ag + (size_t)64*K);
        const __nv_bfloat16* bg = Bw + (size_t)(bcol + r0c) * K + it*BK_ + c0c;
        cp_async16(smem_u32(&Bs[buf][r0c][c0c]),      bg);
        cp_async16(smem_u32(&Bs[buf][r0c+64][c0c]),   bg + (size_t)64*K);
    };

    float acc[2][8][4];
    #pragma unroll
    for (int mi = 0; mi < 2; mi++)
        #pragma unroll
        for (int ni = 0; ni < 8; ni++)
            #pragma unroll
            for (int k = 0; k < 4; k++) acc[mi][ni][k] = 0.f;

    load_tile(0, 0); cp_commit();
    load_tile(1, 1); cp_commit();

    for (int it = 0; it < NIT; ++it) {
        cp_wait1();
        __syncthreads();
        int cur = it & 1;
        #pragma unroll
        for (int kk = 0; kk < 2; kk++) {
            int k0 = kk * 16;
            uint32_t af[2][4], bfr[8][2];
            #pragma unroll
            for (int mi = 0; mi < 2; mi++) {
                uint32_t addr = smem_u32(&As[cur][wm*32 + mi*16 + (lane & 15)]
                                                [k0 + (lane >> 4) * 8]);
                ldmx4(af[mi][0], af[mi][1], af[mi][2], af[mi][3], addr);
            }
            #pragma unroll
            for (int ni = 0; ni < 8; ni++) {
                uint32_t addr = smem_u32(&Bs[cur][wn*64 + ni*8 + (lane & 7)]
                                                [k0 + ((lane >> 3) & 1) * 8]);
                ldmx2(bfr[ni][0], bfr[ni][1], addr);
            }
            #pragma unroll
            for (int mi = 0; mi < 2; mi++)
                #pragma unroll
                for (int ni = 0; ni < 8; ni++)
                    mma_bf16(acc[mi][ni], af[mi], bfr[ni]);
        }
        __syncthreads();
        if (it + 2 < NIT) load_tile(it + 2, cur);
        cp_commit();
    }

    int gq = lane >> 2, tq = lane & 3;
    if (bcol < 256) {
        #pragma unroll
        for (int mi = 0; mi < 2; mi++)
            #pragma unroll
            for (int half = 0; half < 2; half++) {
                int row = brow + wm*32 + mi*16 + half*8 + gq;
                int bb  = row / LQ_;
                int rem = row - bb*LQ_;
                int d   = rem >> 10;
                int pix = rem & 1023;
                size_t tokbase = ((size_t)((bb*NL_ + d)*NH_) * HW_ + pix) * HD_;
                #pragma unroll
                for (int ni = 0; ni < 8; ni++) {
                    int col = bcol + wn*64 + ni*8 + tq*2;
                    int h  = col >> 5;
                    int hd = col & 31;
                    float v0 = acc[mi][ni][half*2 + 0] + bv[col];
                    float v1 = acc[mi][ni][half*2 + 1] + bv[col + 1];
                    __nv_bfloat162 o;
                    o.x = __float2bfloat16(v0);
                    o.y = __float2bfloat16(v1);
                    *(__nv_bfloat162*)&g_valh[tokbase + (size_t)h*HW_*HD_ + hd] = o;
                }
            }
    } else if (bcol < 1536) {
        #pragma unroll
        for (int mi = 0; mi < 2; mi++)
            #pragma unroll
            for (int half = 0; half < 2; half++) {
                int row = brow + wm*32 + mi*16 + half*8 + gq;
                #pragma unroll
                for (int ni = 0; ni < 8; ni++) {
                    int col = bcol - 256 + wn*64 + ni*8 + tq*2;
                    float2 o;
                    o.x = acc[mi][ni][half*2 + 0] + bo[col];
                    o.y = acc[mi][ni][half*2 + 1] + bo[col + 1];
                    *(float2*)&g_off[(size_t)row * 1280 + col] = o;
                }
            }
    } else {
        #pragma unroll
        for (int mi = 0; mi < 2; mi++)
            #pragma unroll
            for (int half = 0; half < 2; half++) {
                int row = brow + wm*32 + mi*16 + half*8 + gq;
                #pragma unroll
                for (int ni = 0; ni < 8; ni++) {
                    int col = bcol - 1536 + wn*64 + ni*8 + tq*2;
                    float2 o;
                    o.x = acc[mi][ni][half*2 + 0] + ba[col];
                    o.y = acc[mi][ni][half*2 + 1] + ba[col + 1];
                    *(float2*)&g_attn[(size_t)row * 640 + col] = o;
                }
            }
    }
}

// ---------------------------------------------------------------------------
// FUSED softmax + prep + gather. Block = token, warp = head.
// Records: per (point, corner) uint32 = byte_off(u16) | bf16_weight<<16.
// Gather: 2 pts/iter, lane=(pt,yr,xh,cg), LDG.128 = 8 chans of one corner,
// f32x2 packed FMA accumulate, shfl reduce, lanes 0-3 store uint4.
// ---------------------------------------------------------------------------
#define PTP_ (PTS_+8)   // padded point stride (bank-conflict-free corner reads)

__global__ void __launch_bounds__(256) sample_fused_kernel(const float* __restrict__ ref)
{
    __shared__ uint32_t s_rec[NH_][4][PTP_];

    int r    = blockIdx.x;
    int h    = threadIdx.x >> 5;
    int lane = threadIdx.x & 31;
    int b    = r / LQ_;

    // ---- Phase 1: softmax + per-corner record build ----
    {
        const float* p = g_attn + (size_t)r * (NH_*PTS_) + h * PTS_;
        float v0 = p[lane];
        float v1 = p[lane + 32];
        float v2 = (lane < 16) ? p[lane + 64] : -1e30f;
        float mx = fmaxf(v0, fmaxf(v1, v2));
        #pragma unroll
        for (int o = 16; o > 0; o >>= 1) mx = fmaxf(mx, __shfl_xor_sync(0xffffffffu, mx, o));
        float e0 = expf(v0 - mx);
        float e1 = expf(v1 - mx);
        float e2 = (lane < 16) ? expf(v2 - mx) : 0.f;
        float s = e0 + e1 + e2;
        #pragma unroll
        for (int o = 16; o > 0; o >>= 1) s += __shfl_xor_sync(0xffffffffu, s, o);
        float inv = 1.f / s;
        float prob[3] = { e0 * inv, e1 * inv, e2 * inv };

        const float2* offp = (const float2*)(g_off + (size_t)r * (NH_*PTS_*2) + h * (PTS_*2));
        const float* refr = ref + (size_t)r * (NL_*2);

        #pragma unroll
        for (int j = 0; j < 3; j++) {
            int it = lane + j*32;
            if (it < PTS_) {
                int l = it >> 4;
                float2 o2 = offp[it];
                float px = refr[l*2 + 0] * (float)W_ + o2.x - 0.5f;
                float py = refr[l*2 + 1] * (float)H_ + o2.y - 0.5f;
                float x0f = floorf(px), y0f = floorf(py);
                float fx = px - x0f, fy = py - y0f;
                int x0 = (int)x0f, y0 = (int)y0f;
                float aw = prob[j];
                float w00 = aw*(1.f-fy)*(1.f-fx);
                float w01 = aw*(1.f-fy)*fx;
                float w10 = aw*fy*(1.f-fx);
                float w11 = aw*fy*fx;
                if (!(((unsigned)y0     < (unsigned)H_) && ((unsigned)x0     < (unsigned)W_))) w00 = 0.f;
                if (!(((unsigned)y0     < (unsigned)H_) && ((unsigned)(x0+1) < (unsigned)W_))) w01 = 0.f;
                if (!(((unsigned)(y0+1) < (unsigned)H_) && ((unsigned)x0     < (unsigned)W_))) w10 = 0.f;
                if (!(((unsigned)(y0+1) < (unsigned)H_) && ((unsigned)(x0+1) < (unsigned)W_))) w11 = 0.f;
                int xc0 = min(max(x0,     0), W_-1);
                int xc1 = min(max(x0 + 1, 0), W_-1);
                int yc0 = min(max(y0,     0), H_-1);
                int yc1 = min(max(y0 + 1, 0), H_-1);
                // byte offsets within a level plane: pix * 64 bytes (fits u16)
                uint32_t o00 = (uint32_t)(yc0*W_ + xc0) << 6;
                uint32_t o01 = (uint32_t)(yc0*W_ + xc1) << 6;
                uint32_t o10 = (uint32_t)(yc1*W_ + xc0) << 6;
                uint32_t o11 = (uint32_t)(yc1*W_ + xc1) << 6;
                s_rec[h][0][it] = o00 | ((uint32_t)__bfloat16_as_ushort(__float2bfloat16(w00)) << 16);
                s_rec[h][1][it] = o01 | ((uint32_t)__bfloat16_as_ushort(__float2bfloat16(w01)) << 16);
                s_rec[h][2][it] = o10 | ((uint32_t)__bfloat16_as_ushort(__float2bfloat16(w10)) << 16);
                s_rec[h][3][it] = o11 | ((uint32_t)__bfloat16_as_ushort(__float2bfloat16(w11)) << 16);
            }
        }
    }
    __syncwarp();

    // ---- Phase 2: gather, 2 points per iteration ----
    int hw     = lane >> 4;         // which of the 2 points this iter
    int corner = (lane >> 2) & 3;   // (yr, xh)
    int cg     = lane & 3;          // channel group (8 chans = 16 B)

    const char* vb0 = (const char*)(g_valh
        + (size_t)((b*NL_)*NH_ + h) * (HW_*HD_)) + cg*16;
    const uint32_t* recs = s_rec[h][corner];

    uint64_t acc0 = 0ull, acc1 = 0ull, acc2 = 0ull, acc3 = 0ull;
    #pragma unroll
    for (int l = 0; l < NL_; l++) {
        const char* vl = vb0 + (size_t)l * (LVL_STRIDE_*2);
        #pragma unroll
        for (int i = 0; i < NP_/2; i++) {
            uint32_t rec = recs[l*NP_ + 2*i + hw];
            uint32_t whi = rec & 0xFFFF0000u;
            uint64_t wpk = pack2(whi, whi);
            uint4 v = *(const uint4*)(vl + (rec & 0xFFFFu));
            fma2(acc0, pack2(v.x << 16, v.x & 0xFFFF0000u), wpk);
            fma2(acc1, pack2(v.y << 16, v.y & 0xFFFF0000u), wpk);
            fma2(acc2, pack2(v.z << 16, v.z & 0xFFFF0000u), wpk);
            fma2(acc3, pack2(v.w << 16, v.w & 0xFFFF0000u), wpk);
        }
    }
    float a0,a1,a2,a3,a4,a5,a6,a7;
    unpack2(acc0, a0, a1);
    unpack2(acc1, a2, a3);
    unpack2(acc2, a4, a5);
    unpack2(acc3, a6, a7);
    #pragma unroll
    for (int o = 16; o >= 4; o >>= 1) {
        a0 += __shfl_xor_sync(0xffffffffu, a0, o);
        a1 += __shfl_xor_sync(0xffffffffu, a1, o);
        a2 += __shfl_xor_sync(0xffffffffu, a2, o);
        a3 += __shfl_xor_sync(0xffffffffu, a3, o);
        a4 += __shfl_xor_sync(0xffffffffu, a4, o);
        a5 += __shfl_xor_sync(0xffffffffu, a5, o);
        a6 += __shfl_xor_sync(0xffffffffu, a6, o);
        a7 += __shfl_xor_sync(0xffffffffu, a7, o);
    }
    if (lane < 4) {
        __nv_bfloat162 o0, o1, o2, o3;
        o0.x = __float2bfloat16(a0); o0.y = __float2bfloat16(a1);
        o1.x = __float2bfloat16(a2); o1.y = __float2bfloat16(a3);
        o2.x = __float2bfloat16(a4); o2.y = __float2bfloat16(a5);
        o3.x = __float2bfloat16(a6); o3.y = __float2bfloat16(a7);
        uint4 st;
        st.x = *(uint32_t*)&o0; st.y = *(uint32_t*)&o1;
        st.z = *(uint32_t*)&o2; st.w = *(uint32_t*)&o3;
        *(uint4*)(g_samp + (size_t)r*C_ + h*HD_ + cg*8) = st;
    }
}

// ---------------------------------------------------------------------------
// Launch
// ---------------------------------------------------------------------------
extern "C" void kernel_launch(void* const* d_in, const int* in_sizes, int n_in,
                              void* d_out, int out_size)
{
    const float* x     = (const float*)d_in[0];
    const float* ref   = (const float*)d_in[1];
    const float* n3g   = (const float*)d_in[4];
    const float* n3b   = (const float*)d_in[5];
    const float* n4g   = (const float*)d_in[6];
    const float* n4b   = (const float*)d_in[7];
    const float* w_off = (const float*)d_in[8];
    const float* b_off = (const float*)d_in[9];
    const float* w_attn= (const float*)d_in[10];
    const float* b_attn= (const float*)d_in[11];
    const float* w_val = (const float*)d_in[12];
    const float* b_val = (const float*)d_in[13];
    const float* w_out = (const float*)d_in[14];
    const float* b_out = (const float*)d_in[15];
    const float* w_fc1 = (const float*)d_in[16];
    const float* b_fc1 = (const float*)d_in[17];
    const float* w_fc2 = (const float*)d_in[18];
    const float* b_fc2 = (const float*)d_in[19];
    float* out = (float*)d_out;

    __nv_bfloat16 *p_q, *p_samp, *p_h, *p_mlp;
    __nv_bfloat16 *p_wproj, *p_wout, *p_wfc1, *p_wfc2;
    cudaGetSymbolAddress((void**)&p_q,    g_q);
    cudaGetSymbolAddress((void**)&p_samp, g_samp);
    cudaGetSymbolAddress((void**)&p_h,    g_h);
    cudaGetSymbolAddress((void**)&p_mlp,  g_mlp);
    cudaGetSymbolAddress((void**)&p_wproj,g_wproj);
    cudaGetSymbolAddress((void**)&p_wout, g_wout);
    cudaGetSymbolAddress((void**)&p_wfc1, g_wfc1);
    cudaGetSymbolAddress((void**)&p_wfc2, g_wfc2);

    tcvt6_kernel<<<1120, dim3(32,32)>>>(
        w_val, w_off, w_attn, w_out, w_fc1, w_fc2,
        p_wproj, p_wout, p_wfc1, p_wfc2);

    // 1) LN3 -> q (bf16)
    ln_kernel<<<M_, 256>>>(x, n3g, n3b, p_q);

    // 2) fused projections: val (head-major bf16) + offsets + attn logits
    gemm_proj<<<dim3(NPROJ_/128, M_/128), 256>>>(p_q, b_val, b_off, b_attn);

    // 3) fused softmax + prep + gather -> g_samp (bf16)
    sample_fused_kernel<<<M_, 256>>>(ref);

    // 4) out projection + residual(x) -> d_out (fp32)
    gemm_hmma<0,1,0><<<dim3(C_/128, M_/128), 256>>>(
        M_, C_, C_, p_samp, p_wout, b_out, x, out, nullptr);

    // 5) LN4 -> h (bf16)
    ln_kernel<<<M_, 256>>>(out, n4g, n4b, p_h);

    // 6) fc1 + GELU -> bf16
    gemm_hmma<1,0,1><<<dim3(MLP_H_/128, M_/128), 256>>>(
        M_, MLP_H_, C_, p_h, p_wfc1, b_fc1, nullptr, nullptr, p_mlp);

    // 7) fc2 + residual(d_out) -> d_out (fp32, in-place elementwise-safe)
    gemm_hmma<0,1,0><<<dim3(C_/128, M_/128), 256>>>(
        M_, C_, MLP_H_, p_mlp, p_wfc2, b_fc2, out, out, nullptr);
}